// round 8
// baseline (speedup 1.0000x reference)
#include <cuda_runtime.h>
#include <cuda_bf16.h>
#include <stdint.h>

// Problem constants (fixed by the dataset)
#define NN 100000
#define CC 64
#define EE 1200000
#define GG 256
#define EPS 1e-5f

// ---------------------------------------------------------------------------
// Scratch (device globals; no cudaMalloc allowed). 16B-aligned.
// ---------------------------------------------------------------------------
__device__ __align__(16) float g_agg[NN * CC];     // neighbor-sum accumulator
__device__ __align__(16) float g_deg[NN];          // in-degree
__device__ __align__(16) float g_h[NN * CC];       // SAGE output
__device__ __align__(16) float g_tact[NN * 8];     // relu(x @ a1^T + a1_b)
__device__ __align__(16) float g_mean[GG * CC];    // per-graph mean
__device__ __align__(16) float g_rstd[GG * CC];    // per-graph rsqrt(var+eps)

// ---------------------------------------------------------------------------
// K0: zero agg + deg
// ---------------------------------------------------------------------------
__global__ void k0_zero(int n4, int n)
{
    int i = blockIdx.x * blockDim.x + threadIdx.x;
    if (i < n4) reinterpret_cast<float4*>(g_agg)[i] = make_float4(0.f, 0.f, 0.f, 0.f);
    if (i < n)  g_deg[i] = 0.f;
}

// ---------------------------------------------------------------------------
// K1: edge scatter. 4 threads per edge, each handles 4 float4 chunks.
// red.global.add.v4.f32: vector reduction, no return value.
// edge_index is int32 (JAX with x64 disabled downgrades int64 -> int32).
// ---------------------------------------------------------------------------
__device__ __forceinline__ void red_add_v4(float* addr, float4 v)
{
    asm volatile("red.global.add.v4.f32 [%0], {%1, %2, %3, %4};"
                 :: "l"(addr), "f"(v.x), "f"(v.y), "f"(v.z), "f"(v.w)
                 : "memory");
}

__global__ void k1_edges(const float* __restrict__ x,
                         const int* __restrict__ ei, int E)
{
    int i = blockIdx.x * blockDim.x + threadIdx.x;
    if (i >= 4 * E) return;
    int e = i >> 2;
    int q = i & 3;
    int s = ei[e];
    int d = ei[E + e];
    const float4* xs = reinterpret_cast<const float4*>(x) + (size_t)s * 16 + q * 4;
    float*        ad = g_agg + (size_t)d * 64 + q * 16;
#pragma unroll
    for (int c = 0; c < 4; c++) {
        float4 v = __ldg(xs + c);
        red_add_v4(ad + c * 4, v);
    }
    if (q == 0) atomicAdd(&g_deg[d], 1.0f);
}

// ---------------------------------------------------------------------------
// K2: per-node fused GEMM (proven R5 FFMA form):
//   h = (agg/max(deg,1)) @ Wl^T + bl + x @ Wr^T        -> g_h
//   tact = relu(x @ a1_w^T + a1_b)                      -> g_tact
// Thread-per-node; 64 fp32 accumulators; weights in shared, transposed,
// read as uniform (broadcast) LDS.128.
// ---------------------------------------------------------------------------
__device__ __forceinline__ float f4get(const float4& v, int u)
{
    switch (u) { case 0: return v.x; case 1: return v.y; case 2: return v.z; default: return v.w; }
}

__global__ __launch_bounds__(256) void k2_node_gemm(
    const float* __restrict__ x,
    const float* __restrict__ Wl, const float* __restrict__ bl,
    const float* __restrict__ Wr,
    const float* __restrict__ a1w, const float* __restrict__ a1b, int N)
{
    __shared__ __align__(16) float sWl[64][64];  // [k][j] = Wl[j][k]
    __shared__ __align__(16) float sWr[64][64];  // [k][j] = Wr[j][k]
    __shared__ __align__(16) float sA1[64][8];   // [k][r] = a1w[r][k]
    __shared__ float sBl[64];

    for (int i = threadIdx.x; i < 4096; i += 256) {
        int j = i & 63, k = i >> 6;
        sWl[k][j] = Wl[j * 64 + k];
        sWr[k][j] = Wr[j * 64 + k];
    }
    for (int i = threadIdx.x; i < 512; i += 256) {
        int r = i & 7, k = i >> 3;
        sA1[k][r] = a1w[r * 64 + k];
    }
    if (threadIdx.x < 64) sBl[threadIdx.x] = bl[threadIdx.x];
    __syncthreads();

    int n = blockIdx.x * 256 + threadIdx.x;
    if (n >= N) return;

    float acc[64];
#pragma unroll
    for (int j = 0; j < 64; j++) acc[j] = sBl[j];
    float t[8];
#pragma unroll
    for (int r = 0; r < 8; r++) t[r] = __ldg(a1b + r);

    float inv = 1.0f / fmaxf(g_deg[n], 1.0f);
    const float4* xr = reinterpret_cast<const float4*>(x) + (size_t)n * 16;
    const float4* ar = reinterpret_cast<const float4*>(g_agg) + (size_t)n * 16;

#pragma unroll 1
    for (int k4 = 0; k4 < 16; k4++) {
        float4 xv = __ldg(xr + k4);
        float4 av = ar[k4];
        float ax[4] = { av.x * inv, av.y * inv, av.z * inv, av.w * inv };
        float xx[4] = { xv.x, xv.y, xv.z, xv.w };
#pragma unroll
        for (int kk = 0; kk < 4; kk++) {
            int k = k4 * 4 + kk;
            float ak = ax[kk], xk = xx[kk];
            const float4* wl4 = reinterpret_cast<const float4*>(&sWl[k][0]);
            const float4* wr4 = reinterpret_cast<const float4*>(&sWr[k][0]);
#pragma unroll
            for (int j4 = 0; j4 < 16; j4++) {
                float4 wl = wl4[j4];
                float4 wr = wr4[j4];
                acc[j4 * 4 + 0] = fmaf(ak, wl.x, fmaf(xk, wr.x, acc[j4 * 4 + 0]));
                acc[j4 * 4 + 1] = fmaf(ak, wl.y, fmaf(xk, wr.y, acc[j4 * 4 + 1]));
                acc[j4 * 4 + 2] = fmaf(ak, wl.z, fmaf(xk, wr.z, acc[j4 * 4 + 2]));
                acc[j4 * 4 + 3] = fmaf(ak, wl.w, fmaf(xk, wr.w, acc[j4 * 4 + 3]));
            }
            const float4* a14 = reinterpret_cast<const float4*>(&sA1[k][0]);
            float4 p = a14[0], q = a14[1];
            t[0] = fmaf(xk, p.x, t[0]); t[1] = fmaf(xk, p.y, t[1]);
            t[2] = fmaf(xk, p.z, t[2]); t[3] = fmaf(xk, p.w, t[3]);
            t[4] = fmaf(xk, q.x, t[4]); t[5] = fmaf(xk, q.y, t[5]);
            t[6] = fmaf(xk, q.z, t[6]); t[7] = fmaf(xk, q.w, t[7]);
        }
    }

    float4* hr = reinterpret_cast<float4*>(g_h) + (size_t)n * 16;
#pragma unroll
    for (int j4 = 0; j4 < 16; j4++)
        hr[j4] = make_float4(acc[j4 * 4 + 0], acc[j4 * 4 + 1], acc[j4 * 4 + 2], acc[j4 * 4 + 3]);

    float4* tr = reinterpret_cast<float4*>(g_tact) + (size_t)n * 2;
    tr[0] = make_float4(fmaxf(t[0], 0.f), fmaxf(t[1], 0.f), fmaxf(t[2], 0.f), fmaxf(t[3], 0.f));
    tr[1] = make_float4(fmaxf(t[4], 0.f), fmaxf(t[5], 0.f), fmaxf(t[6], 0.f), fmaxf(t[7], 0.f));
}

// ---------------------------------------------------------------------------
// K2b: per-graph stats, bandwidth-oriented rebuild.
// One block per graph (batch SORTED int32; binary-search segment).
// 256 threads = 16 row-strides x 16 float4 channel-groups; 2x unrolled ->
// up to 32 float4 loads in flight per thread iteration group.
// Single pass: var(out) = E[h^2] - (2a - a^2)*mean^2.
// ---------------------------------------------------------------------------
__global__ __launch_bounds__(256) void k2b_stats(
    const int* __restrict__ batch,
    const float* __restrict__ gn_alpha, int N)
{
    int g  = blockIdx.x;
    int c4 = threadIdx.x & 15;   // float4 channel group 0..15
    int r  = threadIdx.x >> 4;   // row stride 0..15

    // lower_bound(batch, g) and lower_bound(batch, g+1)
    int lo = 0, hi = N;
    while (lo < hi) { int mid = (lo + hi) >> 1; if (batch[mid] < g) lo = mid + 1; else hi = mid; }
    int start = lo;
    lo = start; hi = N;
    while (lo < hi) { int mid = (lo + hi) >> 1; if (batch[mid] < g + 1) lo = mid + 1; else hi = mid; }
    int end = lo;

    const float4* h4 = reinterpret_cast<const float4*>(g_h);
    float4 s0 = make_float4(0.f, 0.f, 0.f, 0.f), q0 = s0;
    float4 s1 = s0, q1 = s0;

    int i = start + r;
    for (; i + 16 < end; i += 32) {
        float4 a = h4[(size_t)i * 16 + c4];
        float4 b = h4[(size_t)(i + 16) * 16 + c4];
        s0.x += a.x; s0.y += a.y; s0.z += a.z; s0.w += a.w;
        q0.x = fmaf(a.x, a.x, q0.x); q0.y = fmaf(a.y, a.y, q0.y);
        q0.z = fmaf(a.z, a.z, q0.z); q0.w = fmaf(a.w, a.w, q0.w);
        s1.x += b.x; s1.y += b.y; s1.z += b.z; s1.w += b.w;
        q1.x = fmaf(b.x, b.x, q1.x); q1.y = fmaf(b.y, b.y, q1.y);
        q1.z = fmaf(b.z, b.z, q1.z); q1.w = fmaf(b.w, b.w, q1.w);
    }
    for (; i < end; i += 16) {
        float4 a = h4[(size_t)i * 16 + c4];
        s0.x += a.x; s0.y += a.y; s0.z += a.z; s0.w += a.w;
        q0.x = fmaf(a.x, a.x, q0.x); q0.y = fmaf(a.y, a.y, q0.y);
        q0.z = fmaf(a.z, a.z, q0.z); q0.w = fmaf(a.w, a.w, q0.w);
    }
    s0.x += s1.x; s0.y += s1.y; s0.z += s1.z; s0.w += s1.w;
    q0.x += q1.x; q0.y += q1.y; q0.z += q1.z; q0.w += q1.w;

    __shared__ __align__(16) float4 sS[16][16];
    __shared__ __align__(16) float4 sQ[16][16];
    sS[r][c4] = s0;
    sQ[r][c4] = q0;
    __syncthreads();

    // tree reduce over the 16 row-strides
    for (int off = 8; off > 0; off >>= 1) {
        if (r < off) {
            float4 a = sS[r][c4], b = sS[r + off][c4];
            sS[r][c4] = make_float4(a.x + b.x, a.y + b.y, a.z + b.z, a.w + b.w);
            float4 c = sQ[r][c4], d = sQ[r + off][c4];
            sQ[r][c4] = make_float4(c.x + d.x, c.y + d.y, c.z + d.z, c.w + d.w);
        }
        __syncthreads();
    }

    if (r == 0) {
        float4 s = sS[0][c4];
        float4 q = sQ[0][c4];
        float cnt = fmaxf((float)(end - start), 1.0f);
        float rinv = 1.0f / cnt;
        float4 al = __ldg(reinterpret_cast<const float4*>(gn_alpha) + c4);
        float mu[4]  = { s.x * rinv, s.y * rinv, s.z * rinv, s.w * rinv };
        float eq[4]  = { q.x * rinv, q.y * rinv, q.z * rinv, q.w * rinv };
        float a4[4]  = { al.x, al.y, al.z, al.w };
        float m_out[4], r_out[4];
#pragma unroll
        for (int u = 0; u < 4; u++) {
            float fac = 2.0f * a4[u] - a4[u] * a4[u];
            float var = fmaxf(eq[u] - fac * mu[u] * mu[u], 0.0f);
            m_out[u] = mu[u];
            r_out[u] = rsqrtf(var + EPS);
        }
        reinterpret_cast<float4*>(g_mean)[g * 16 + c4] =
            make_float4(m_out[0], m_out[1], m_out[2], m_out[3]);
        reinterpret_cast<float4*>(g_rstd)[g * 16 + c4] =
            make_float4(r_out[0], r_out[1], r_out[2], r_out[3]);
    }
}

// ---------------------------------------------------------------------------
// K3: finalize. thread per (node, 4-channel chunk).
//   y    = w*(h - mean*alpha)*rstd + b
//   gate = sigmoid(tact @ a2_w^T + a2_b)
//   out  = relu(y + gate*x)
// ---------------------------------------------------------------------------
__global__ __launch_bounds__(256) void k3_finalize(
    const float* __restrict__ x, const int* __restrict__ batch,
    const float* __restrict__ gnw, const float* __restrict__ gnb,
    const float* __restrict__ gna,
    const float* __restrict__ a2w, const float* __restrict__ a2b,
    float* __restrict__ out, int N)
{
    int i = blockIdx.x * blockDim.x + threadIdx.x;
    if (i >= N * 16) return;
    int n  = i >> 4;
    int c4 = i & 15;
    int g  = batch[n];

    float4 hv = reinterpret_cast<const float4*>(g_h)[(size_t)n * 16 + c4];
    float4 xv = reinterpret_cast<const float4*>(x)[(size_t)n * 16 + c4];
    float4 mu = reinterpret_cast<const float4*>(g_mean)[g * 16 + c4];
    float4 rs = reinterpret_cast<const float4*>(g_rstd)[g * 16 + c4];
    float4 al = __ldg(reinterpret_cast<const float4*>(gna) + c4);
    float4 w4 = __ldg(reinterpret_cast<const float4*>(gnw) + c4);
    float4 b4 = __ldg(reinterpret_cast<const float4*>(gnb) + c4);
    float4 t0 = reinterpret_cast<const float4*>(g_tact)[(size_t)n * 2];
    float4 t1 = reinterpret_cast<const float4*>(g_tact)[(size_t)n * 2 + 1];
    float4 b2 = __ldg(reinterpret_cast<const float4*>(a2b) + c4);

    float res[4];
#pragma unroll
    for (int u = 0; u < 4; u++) {
        int j = c4 * 4 + u;
        float4 wa = __ldg(reinterpret_cast<const float4*>(a2w) + j * 2);
        float4 wb = __ldg(reinterpret_cast<const float4*>(a2w) + j * 2 + 1);
        float z = wa.x * t0.x + wa.y * t0.y + wa.z * t0.z + wa.w * t0.w
                + wb.x * t1.x + wb.y * t1.y + wb.z * t1.z + wb.w * t1.w
                + f4get(b2, u);
        float gate = 1.0f / (1.0f + __expf(-z));
        float y = f4get(w4, u) * (f4get(hv, u) - f4get(mu, u) * f4get(al, u)) * f4get(rs, u)
                + f4get(b4, u);
        res[u] = fmaxf(y + gate * f4get(xv, u), 0.0f);
    }
    reinterpret_cast<float4*>(out)[(size_t)n * 16 + c4] =
        make_float4(res[0], res[1], res[2], res[3]);
}

// ---------------------------------------------------------------------------
// launch
// ---------------------------------------------------------------------------
extern "C" void kernel_launch(void* const* d_in, const int* in_sizes, int n_in,
                              void* d_out, int out_size)
{
    const float* x     = (const float*)d_in[0];
    const int*   ei    = (const int*)d_in[1];     // int32 (JAX x64 disabled)
    const int*   batch = (const int*)d_in[2];     // int32
    const float* Wl    = (const float*)d_in[3];
    const float* bl    = (const float*)d_in[4];
    const float* Wr    = (const float*)d_in[5];
    const float* gnw   = (const float*)d_in[6];
    const float* gnb   = (const float*)d_in[7];
    const float* gna   = (const float*)d_in[8];
    const float* a1w   = (const float*)d_in[9];
    const float* a1b   = (const float*)d_in[10];
    const float* a2w   = (const float*)d_in[11];
    const float* a2b   = (const float*)d_in[12];
    float*       out   = (float*)d_out;

    int N = in_sizes[0] / CC;          // 100000
    int E = in_sizes[1] / 2;           // 1200000

    // K0: zero agg + deg
    {
        int n4 = (N * CC) / 4;
        k0_zero<<<(n4 + 255) / 256, 256>>>(n4, N);
    }
    // K1: edge scatter
    {
        long long total = (long long)E * 4;
        k1_edges<<<(int)((total + 255) / 256), 256>>>(x, ei, E);
    }
    // K2: node GEMM + attention layer 1
    k2_node_gemm<<<(N + 255) / 256, 256>>>(x, Wl, bl, Wr, a1w, a1b, N);
    // K2b: per-graph stats
    k2b_stats<<<GG, 256>>>(batch, gna, N);
    // K3: finalize
    k3_finalize<<<(N * 16 + 255) / 256, 256>>>(x, batch, gnw, gnb, gna, a2w, a2b, out, N);
}

// round 9
// speedup vs baseline: 1.0802x; 1.0802x over previous
#include <cuda_runtime.h>
#include <cuda_bf16.h>
#include <stdint.h>

// Problem constants (fixed by the dataset)
#define NN 100000
#define CC 64
#define EE 1200000
#define GG 256
#define EPS 1e-5f

// ---------------------------------------------------------------------------
// Scratch (device globals; no cudaMalloc allowed). 16B-aligned.
// ---------------------------------------------------------------------------
__device__ __align__(16) float g_agg[NN * CC];    // neighbor-sum (written by gather)
__device__ __align__(16) float g_deg[NN];         // in-degree (float)
__device__ __align__(16) float g_h[NN * CC];      // SAGE output
__device__ __align__(16) float g_tact[NN * 8];    // relu(x @ a1^T + a1_b)
__device__ __align__(16) float g_mean[GG * CC];   // per-graph mean
__device__ __align__(16) float g_rstd[GG * CC];   // per-graph rsqrt(var+eps)
__device__ __align__(16) float g_stat[GG * 128];  // per-graph partial sum[64]|sq[64]

__device__ __align__(16) int g_cnt[NN];           // in-degree counts
__device__ __align__(16) int g_off[NN + 1];       // CSR offsets
__device__ __align__(16) int g_cur[NN];           // placement cursors
__device__ __align__(16) int g_srcidx[EE];        // CSR: src node per slot
__device__ __align__(16) int g_bsum[512];         // scan block sums
__device__ __align__(16) int g_boff[512];         // scan block offsets

// ---------------------------------------------------------------------------
// kA: zero counts + per-graph stat partials
// ---------------------------------------------------------------------------
__global__ void kA_zero(int N)
{
    int i = blockIdx.x * blockDim.x + threadIdx.x;
    if (i < N) g_cnt[i] = 0;
    if (i < GG * 32) reinterpret_cast<float4*>(g_stat)[i] = make_float4(0.f, 0.f, 0.f, 0.f);
}

// ---------------------------------------------------------------------------
// kB: histogram of in-degree
// ---------------------------------------------------------------------------
__global__ void kB_hist(const int* __restrict__ ei, int E)
{
    int e = blockIdx.x * blockDim.x + threadIdx.x;
    if (e >= E) return;
    atomicAdd(&g_cnt[ei[E + e]], 1);
}

// ---------------------------------------------------------------------------
// kC1/kC2/kC3: 3-phase exclusive scan of g_cnt -> g_off (size N+1), g_cur
// ---------------------------------------------------------------------------
__global__ __launch_bounds__(256) void kC1_scan(int N)
{
    int i = blockIdx.x * 256 + threadIdx.x;
    int lane = threadIdx.x & 31, w = threadIdx.x >> 5;
    int v = (i < N) ? g_cnt[i] : 0;
    int s = v;
#pragma unroll
    for (int o = 1; o < 32; o <<= 1) {
        int t = __shfl_up_sync(0xffffffffu, s, o);
        if (lane >= o) s += t;
    }
    __shared__ int wsum[8], woff[8];
    if (lane == 31) wsum[w] = s;
    __syncthreads();
    if (threadIdx.x == 0) {
        int acc = 0;
#pragma unroll
        for (int k = 0; k < 8; k++) { woff[k] = acc; acc += wsum[k]; }
        wsum[0] = acc;  // block total
    }
    __syncthreads();
    s += woff[w];
    if (i < N) g_off[i + 1] = s;           // within-block inclusive scan
    if (threadIdx.x == 0) g_bsum[blockIdx.x] = wsum[0];
}

__global__ __launch_bounds__(512) void kC2_scan(int nb)
{
    __shared__ int sm[512];
    int t = threadIdx.x;
    int v = (t < nb) ? g_bsum[t] : 0;
    sm[t] = v;
    __syncthreads();
    for (int o = 1; o < 512; o <<= 1) {
        int x = (t >= o) ? sm[t - o] : 0;
        __syncthreads();
        sm[t] += x;
        __syncthreads();
    }
    if (t < nb) g_boff[t] = sm[t] - v;     // exclusive
}

__global__ __launch_bounds__(256) void kC3_scan(int N)
{
    int b = blockIdx.x, tid = threadIdx.x;
    int i = b * 256 + tid;
    int boff = g_boff[b];
    int incl_pre = 0, excl_pre = 0;
    bool ok = (i < N);
    if (ok) {
        incl_pre = g_off[i + 1];
        excl_pre = (tid == 0) ? 0 : g_off[i];   // same-block entry, pre-add
    }
    __syncthreads();
    if (ok) {
        g_off[i + 1] = incl_pre + boff;
        g_cur[i]     = excl_pre + boff;
        if (i == 0) g_off[0] = 0;
    }
}

// ---------------------------------------------------------------------------
// kD: place src ids into CSR slots
// ---------------------------------------------------------------------------
__global__ void kD_place(const int* __restrict__ ei, int E)
{
    int e = blockIdx.x * blockDim.x + threadIdx.x;
    if (e >= E) return;
    int s = ei[e];
    int d = ei[E + e];
    int pos = atomicAdd(&g_cur[d], 1);
    g_srcidx[pos] = s;
}

// ---------------------------------------------------------------------------
// kE: gather-aggregate. 16 threads per node; each owns one float4 channel
// group. Coalesced reads of x (L2-resident), no feature atomics.
// ---------------------------------------------------------------------------
__global__ __launch_bounds__(256) void kE_gather(const float* __restrict__ x, int N)
{
    int gidx = blockIdx.x * 256 + threadIdx.x;
    int n  = gidx >> 4;
    int c4 = gidx & 15;
    if (n >= N) return;
    int off = g_off[n], end = g_off[n + 1];

    const float4* x4 = reinterpret_cast<const float4*>(x);
    float4 a0 = make_float4(0.f, 0.f, 0.f, 0.f);
    float4 a1 = a0;

    int k = off;
    for (; k + 1 < end; k += 2) {
        int s0 = g_srcidx[k];
        int s1 = g_srcidx[k + 1];
        float4 v0 = __ldg(x4 + (size_t)s0 * 16 + c4);
        float4 v1 = __ldg(x4 + (size_t)s1 * 16 + c4);
        a0.x += v0.x; a0.y += v0.y; a0.z += v0.z; a0.w += v0.w;
        a1.x += v1.x; a1.y += v1.y; a1.z += v1.z; a1.w += v1.w;
    }
    if (k < end) {
        int s0 = g_srcidx[k];
        float4 v0 = __ldg(x4 + (size_t)s0 * 16 + c4);
        a0.x += v0.x; a0.y += v0.y; a0.z += v0.z; a0.w += v0.w;
    }
    a0.x += a1.x; a0.y += a1.y; a0.z += a1.z; a0.w += a1.w;

    reinterpret_cast<float4*>(g_agg)[(size_t)n * 16 + c4] = a0;
    if (c4 == 0) g_deg[n] = (float)(end - off);
}

// ---------------------------------------------------------------------------
// K2: per-node fused GEMM (proven FFMA form):
//   h = (agg/max(deg,1)) @ Wl^T + bl + x @ Wr^T        -> g_h
//   tact = relu(x @ a1_w^T + a1_b)                      -> g_tact
// ---------------------------------------------------------------------------
__device__ __forceinline__ float f4get(const float4& v, int u)
{
    switch (u) { case 0: return v.x; case 1: return v.y; case 2: return v.z; default: return v.w; }
}

__global__ __launch_bounds__(256) void k2_node_gemm(
    const float* __restrict__ x,
    const float* __restrict__ Wl, const float* __restrict__ bl,
    const float* __restrict__ Wr,
    const float* __restrict__ a1w, const float* __restrict__ a1b, int N)
{
    __shared__ __align__(16) float sWl[64][64];  // [k][j] = Wl[j][k]
    __shared__ __align__(16) float sWr[64][64];  // [k][j] = Wr[j][k]
    __shared__ __align__(16) float sA1[64][8];   // [k][r] = a1w[r][k]
    __shared__ float sBl[64];

    for (int i = threadIdx.x; i < 4096; i += 256) {
        int j = i & 63, k = i >> 6;
        sWl[k][j] = Wl[j * 64 + k];
        sWr[k][j] = Wr[j * 64 + k];
    }
    for (int i = threadIdx.x; i < 512; i += 256) {
        int r = i & 7, k = i >> 3;
        sA1[k][r] = a1w[r * 64 + k];
    }
    if (threadIdx.x < 64) sBl[threadIdx.x] = bl[threadIdx.x];
    __syncthreads();

    int n = blockIdx.x * 256 + threadIdx.x;
    if (n >= N) return;

    float acc[64];
#pragma unroll
    for (int j = 0; j < 64; j++) acc[j] = sBl[j];
    float t[8];
#pragma unroll
    for (int r = 0; r < 8; r++) t[r] = __ldg(a1b + r);

    float inv = 1.0f / fmaxf(g_deg[n], 1.0f);
    const float4* xr = reinterpret_cast<const float4*>(x) + (size_t)n * 16;
    const float4* ar = reinterpret_cast<const float4*>(g_agg) + (size_t)n * 16;

#pragma unroll 1
    for (int k4 = 0; k4 < 16; k4++) {
        float4 xv = __ldg(xr + k4);
        float4 av = ar[k4];
        float ax[4] = { av.x * inv, av.y * inv, av.z * inv, av.w * inv };
        float xx[4] = { xv.x, xv.y, xv.z, xv.w };
#pragma unroll
        for (int kk = 0; kk < 4; kk++) {
            int k = k4 * 4 + kk;
            float ak = ax[kk], xk = xx[kk];
            const float4* wl4 = reinterpret_cast<const float4*>(&sWl[k][0]);
            const float4* wr4 = reinterpret_cast<const float4*>(&sWr[k][0]);
#pragma unroll
            for (int j4 = 0; j4 < 16; j4++) {
                float4 wl = wl4[j4];
                float4 wr = wr4[j4];
                acc[j4 * 4 + 0] = fmaf(ak, wl.x, fmaf(xk, wr.x, acc[j4 * 4 + 0]));
                acc[j4 * 4 + 1] = fmaf(ak, wl.y, fmaf(xk, wr.y, acc[j4 * 4 + 1]));
                acc[j4 * 4 + 2] = fmaf(ak, wl.z, fmaf(xk, wr.z, acc[j4 * 4 + 2]));
                acc[j4 * 4 + 3] = fmaf(ak, wl.w, fmaf(xk, wr.w, acc[j4 * 4 + 3]));
            }
            const float4* a14 = reinterpret_cast<const float4*>(&sA1[k][0]);
            float4 p = a14[0], q = a14[1];
            t[0] = fmaf(xk, p.x, t[0]); t[1] = fmaf(xk, p.y, t[1]);
            t[2] = fmaf(xk, p.z, t[2]); t[3] = fmaf(xk, p.w, t[3]);
            t[4] = fmaf(xk, q.x, t[4]); t[5] = fmaf(xk, q.y, t[5]);
            t[6] = fmaf(xk, q.z, t[6]); t[7] = fmaf(xk, q.w, t[7]);
        }
    }

    float4* hr = reinterpret_cast<float4*>(g_h) + (size_t)n * 16;
#pragma unroll
    for (int j4 = 0; j4 < 16; j4++)
        hr[j4] = make_float4(acc[j4 * 4 + 0], acc[j4 * 4 + 1], acc[j4 * 4 + 2], acc[j4 * 4 + 3]);

    float4* tr = reinterpret_cast<float4*>(g_tact) + (size_t)n * 2;
    tr[0] = make_float4(fmaxf(t[0], 0.f), fmaxf(t[1], 0.f), fmaxf(t[2], 0.f), fmaxf(t[3], 0.f));
    tr[1] = make_float4(fmaxf(t[4], 0.f), fmaxf(t[5], 0.f), fmaxf(t[6], 0.f), fmaxf(t[7], 0.f));
}

// ---------------------------------------------------------------------------
// k2b_part: per-graph partial stats, 8 slices per graph (grid = 2048 blocks
// -> full-chip occupancy). Tree-reduce in smem, then red.add.v4 into g_stat.
// ---------------------------------------------------------------------------
__device__ __forceinline__ void red_add_v4(float* addr, float4 v)
{
    asm volatile("red.global.add.v4.f32 [%0], {%1, %2, %3, %4};"
                 :: "l"(addr), "f"(v.x), "f"(v.y), "f"(v.z), "f"(v.w)
                 : "memory");
}

__global__ __launch_bounds__(256) void k2b_part(const int* __restrict__ batch, int N)
{
    int g     = blockIdx.x >> 3;
    int slice = blockIdx.x & 7;
    int c4 = threadIdx.x & 15;
    int r  = threadIdx.x >> 4;

    int lo = 0, hi = N;
    while (lo < hi) { int mid = (lo + hi) >> 1; if (batch[mid] < g) lo = mid + 1; else hi = mid; }
    int start = lo;
    lo = start; hi = N;
    while (lo < hi) { int mid = (lo + hi) >> 1; if (batch[mid] < g + 1) lo = mid + 1; else hi = mid; }
    int end = lo;

    const float4* h4 = reinterpret_cast<const float4*>(g_h);
    float4 s0 = make_float4(0.f, 0.f, 0.f, 0.f), q0 = s0;

    for (int i = start + slice * 16 + r; i < end; i += 128) {
        float4 a = h4[(size_t)i * 16 + c4];
        s0.x += a.x; s0.y += a.y; s0.z += a.z; s0.w += a.w;
        q0.x = fmaf(a.x, a.x, q0.x); q0.y = fmaf(a.y, a.y, q0.y);
        q0.z = fmaf(a.z, a.z, q0.z); q0.w = fmaf(a.w, a.w, q0.w);
    }

    __shared__ __align__(16) float4 sS[16][16];
    __shared__ __align__(16) float4 sQ[16][16];
    sS[r][c4] = s0;
    sQ[r][c4] = q0;
    __syncthreads();
    for (int off = 8; off > 0; off >>= 1) {
        if (r < off) {
            float4 a = sS[r][c4], b = sS[r + off][c4];
            sS[r][c4] = make_float4(a.x + b.x, a.y + b.y, a.z + b.z, a.w + b.w);
            float4 c = sQ[r][c4], d = sQ[r + off][c4];
            sQ[r][c4] = make_float4(c.x + d.x, c.y + d.y, c.z + d.z, c.w + d.w);
        }
        __syncthreads();
    }
    if (r == 0) {
        red_add_v4(&g_stat[g * 128 + c4 * 4], sS[0][c4]);
        red_add_v4(&g_stat[g * 128 + 64 + c4 * 4], sQ[0][c4]);
    }
}

// ---------------------------------------------------------------------------
// k2b_fin: mean/rstd from accumulated stats. 256 blocks x 64 threads.
// ---------------------------------------------------------------------------
__global__ __launch_bounds__(64) void k2b_fin(
    const int* __restrict__ batch, const float* __restrict__ gn_alpha, int N)
{
    int g = blockIdx.x;
    int c = threadIdx.x;
    __shared__ int se[2];
    if (c == 0) {
        int lo = 0, hi = N;
        while (lo < hi) { int mid = (lo + hi) >> 1; if (batch[mid] < g) lo = mid + 1; else hi = mid; }
        se[0] = lo;
        hi = N;
        while (lo < hi) { int mid = (lo + hi) >> 1; if (batch[mid] < g + 1) lo = mid + 1; else hi = mid; }
        se[1] = lo;
    }
    __syncthreads();
    float cnt = fmaxf((float)(se[1] - se[0]), 1.0f);
    float rinv = 1.0f / cnt;
    float sum = g_stat[g * 128 + c];
    float sq  = g_stat[g * 128 + 64 + c];
    float mu = sum * rinv;
    float al = gn_alpha[c];
    float fac = 2.0f * al - al * al;
    float var = fmaxf(sq * rinv - fac * mu * mu, 0.0f);
    g_mean[g * 64 + c] = mu;
    g_rstd[g * 64 + c] = rsqrtf(var + EPS);
}

// ---------------------------------------------------------------------------
// K3: finalize. thread per (node, 4-channel chunk).
// ---------------------------------------------------------------------------
__global__ __launch_bounds__(256) void k3_finalize(
    const float* __restrict__ x, const int* __restrict__ batch,
    const float* __restrict__ gnw, const float* __restrict__ gnb,
    const float* __restrict__ gna,
    const float* __restrict__ a2w, const float* __restrict__ a2b,
    float* __restrict__ out, int N)
{
    int i = blockIdx.x * blockDim.x + threadIdx.x;
    if (i >= N * 16) return;
    int n  = i >> 4;
    int c4 = i & 15;
    int g  = batch[n];

    float4 hv = reinterpret_cast<const float4*>(g_h)[(size_t)n * 16 + c4];
    float4 xv = reinterpret_cast<const float4*>(x)[(size_t)n * 16 + c4];
    float4 mu = reinterpret_cast<const float4*>(g_mean)[g * 16 + c4];
    float4 rs = reinterpret_cast<const float4*>(g_rstd)[g * 16 + c4];
    float4 al = __ldg(reinterpret_cast<const float4*>(gna) + c4);
    float4 w4 = __ldg(reinterpret_cast<const float4*>(gnw) + c4);
    float4 b4 = __ldg(reinterpret_cast<const float4*>(gnb) + c4);
    float4 t0 = reinterpret_cast<const float4*>(g_tact)[(size_t)n * 2];
    float4 t1 = reinterpret_cast<const float4*>(g_tact)[(size_t)n * 2 + 1];
    float4 b2 = __ldg(reinterpret_cast<const float4*>(a2b) + c4);

    float res[4];
#pragma unroll
    for (int u = 0; u < 4; u++) {
        int j = c4 * 4 + u;
        float4 wa = __ldg(reinterpret_cast<const float4*>(a2w) + j * 2);
        float4 wb = __ldg(reinterpret_cast<const float4*>(a2w) + j * 2 + 1);
        float z = wa.x * t0.x + wa.y * t0.y + wa.z * t0.z + wa.w * t0.w
                + wb.x * t1.x + wb.y * t1.y + wb.z * t1.z + wb.w * t1.w
                + f4get(b2, u);
        float gate = 1.0f / (1.0f + __expf(-z));
        float y = f4get(w4, u) * (f4get(hv, u) - f4get(mu, u) * f4get(al, u)) * f4get(rs, u)
                + f4get(b4, u);
        res[u] = fmaxf(y + gate * f4get(xv, u), 0.0f);
    }
    reinterpret_cast<float4*>(out)[(size_t)n * 16 + c4] =
        make_float4(res[0], res[1], res[2], res[3]);
}

// ---------------------------------------------------------------------------
// launch
// ---------------------------------------------------------------------------
extern "C" void kernel_launch(void* const* d_in, const int* in_sizes, int n_in,
                              void* d_out, int out_size)
{
    const float* x     = (const float*)d_in[0];
    const int*   ei    = (const int*)d_in[1];     // int32 (JAX x64 disabled)
    const int*   batch = (const int*)d_in[2];     // int32
    const float* Wl    = (const float*)d_in[3];
    const float* bl    = (const float*)d_in[4];
    const float* Wr    = (const float*)d_in[5];
    const float* gnw   = (const float*)d_in[6];
    const float* gnb   = (const float*)d_in[7];
    const float* gna   = (const float*)d_in[8];
    const float* a1w   = (const float*)d_in[9];
    const float* a1b   = (const float*)d_in[10];
    const float* a2w   = (const float*)d_in[11];
    const float* a2b   = (const float*)d_in[12];
    float*       out   = (float*)d_out;

    int N = in_sizes[0] / CC;          // 100000
    int E = in_sizes[1] / 2;           // 1200000
    int nb = (N + 255) / 256;          // scan blocks (391 <= 512)

    // CSR build
    kA_zero<<<(N + 255) / 256, 256>>>(N);
    kB_hist<<<(E + 255) / 256, 256>>>(ei, E);
    kC1_scan<<<nb, 256>>>(N);
    kC2_scan<<<1, 512>>>(nb);
    kC3_scan<<<nb, 256>>>(N);
    kD_place<<<(E + 255) / 256, 256>>>(ei, E);
    // gather-aggregate
    kE_gather<<<(N * 16 + 255) / 256, 256>>>(x, N);
    // node GEMM + attention layer 1
    k2_node_gemm<<<(N + 255) / 256, 256>>>(x, Wl, bl, Wr, a1w, a1b, N);
    // per-graph stats (partial + finalize)
    k2b_part<<<GG * 8, 256>>>(batch, N);
    k2b_fin<<<GG, 64>>>(batch, gna, N);
    // finalize
    k3_finalize<<<(N * 16 + 255) / 256, 256>>>(x, batch, gnw, gnb, gna, a2w, a2b, out, N);
}

// round 10
// speedup vs baseline: 1.1254x; 1.0418x over previous
#include <cuda_runtime.h>
#include <cuda_bf16.h>
#include <stdint.h>

// Problem constants (fixed by the dataset)
#define NN 100000
#define CC 64
#define EE 1200000
#define GG 256
#define EPS 1e-5f

typedef unsigned long long u64;

#define FLAG_AGG (1ULL << 62)
#define FLAG_PRE (2ULL << 62)
#define VALMASK  ((1ULL << 62) - 1ULL)

// ---------------------------------------------------------------------------
// Scratch (device globals; no cudaMalloc allowed). 16B-aligned.
// ---------------------------------------------------------------------------
__device__ __align__(16) float g_agg[NN * CC];    // neighbor-sum (gather output)
__device__ __align__(16) float g_deg[NN];         // in-degree (float)
__device__ __align__(16) float g_h[NN * CC];      // SAGE output
__device__ __align__(16) float g_tact[NN * 8];    // relu(x @ a1^T + a1_b)
__device__ __align__(16) float g_mean[GG * CC];   // per-graph mean
__device__ __align__(16) float g_rstd[GG * CC];   // per-graph rsqrt(var+eps)
__device__ __align__(16) float g_stat[GG * 128];  // per-graph partial sum[64]|sq[64]

__device__ __align__(16) int g_cnt[NN];           // in-degree counts
__device__ __align__(16) int g_off[NN + 1];       // CSR offsets
__device__ __align__(16) int g_cur[NN];           // placement cursors
__device__ __align__(16) int g_srcidx[EE];        // CSR: src node per slot
__device__ int g_k2b_ctr[GG];                     // last-block-done counters
__device__ volatile u64 g_scanstate[512];         // decoupled-lookback state

// ---------------------------------------------------------------------------
// f32x2 packed math (PTX-only path; ptxas won't auto-fuse)
// ---------------------------------------------------------------------------
__device__ __forceinline__ u64 pack2(float lo, float hi)
{
    u64 r;
    asm("mov.b64 %0, {%1, %2};" : "=l"(r)
        : "r"(__float_as_uint(lo)), "r"(__float_as_uint(hi)));
    return r;
}
__device__ __forceinline__ u64 fma2(u64 a, u64 b, u64 c)
{
    u64 d;
    asm("fma.rn.f32x2 %0, %1, %2, %3;" : "=l"(d) : "l"(a), "l"(b), "l"(c));
    return d;
}
__device__ __forceinline__ float2 unpack2(u64 v)
{
    float2 r;
    uint32_t lo, hi;
    asm("mov.b64 {%0, %1}, %2;" : "=r"(lo), "=r"(hi) : "l"(v));
    r.x = __uint_as_float(lo);
    r.y = __uint_as_float(hi);
    return r;
}

__device__ __forceinline__ void red_add_v4(float* addr, float4 v)
{
    asm volatile("red.global.add.v4.f32 [%0], {%1, %2, %3, %4};"
                 :: "l"(addr), "f"(v.x), "f"(v.y), "f"(v.z), "f"(v.w)
                 : "memory");
}

// ---------------------------------------------------------------------------
// kA: zero counts, stat partials, completion counters, scan state
// ---------------------------------------------------------------------------
__global__ void kA_zero(int N)
{
    int i = blockIdx.x * blockDim.x + threadIdx.x;
    if (i < N) g_cnt[i] = 0;
    if (i < GG * 32) reinterpret_cast<float4*>(g_stat)[i] = make_float4(0.f, 0.f, 0.f, 0.f);
    if (i < GG) g_k2b_ctr[i] = 0;
    if (i < 512) g_scanstate[i] = 0ULL;
}

// ---------------------------------------------------------------------------
// kB: histogram of in-degree
// ---------------------------------------------------------------------------
__global__ void kB_hist(const int* __restrict__ ei, int E)
{
    int e = blockIdx.x * blockDim.x + threadIdx.x;
    if (e >= E) return;
    atomicAdd(&g_cnt[ei[E + e]], 1);
}

// ---------------------------------------------------------------------------
// kScan: single-pass exclusive scan of g_cnt -> g_off[N+1], g_cur
// (decoupled lookback, warp-parallel 32-wide windows)
// ---------------------------------------------------------------------------
__global__ __launch_bounds__(256) void kScan(int N)
{
    int b = blockIdx.x;
    int i = b * 256 + threadIdx.x;
    int lane = threadIdx.x & 31, w = threadIdx.x >> 5;

    int v = (i < N) ? g_cnt[i] : 0;
    int s = v;
#pragma unroll
    for (int o = 1; o < 32; o <<= 1) {
        int t = __shfl_up_sync(0xffffffffu, s, o);
        if (lane >= o) s += t;
    }
    __shared__ int wsum[8], woff[8], sbtot;
    __shared__ u64 sprefix;
    if (lane == 31) wsum[w] = s;
    __syncthreads();
    if (threadIdx.x == 0) {
        int acc = 0;
#pragma unroll
        for (int k = 0; k < 8; k++) { woff[k] = acc; acc += wsum[k]; }
        sbtot = acc;
        // publish block aggregate (block 0 publishes final prefix directly)
        __threadfence();
        g_scanstate[b] = (b == 0 ? FLAG_PRE : FLAG_AGG) | (u64)acc;
        if (b == 0) sprefix = 0ULL;
    }
    __syncthreads();
    int incl = s + woff[w];
    int total = sbtot;

    if (b > 0 && w == 0) {
        long long run = 0;
        int base = b - 1;
        bool done = false;
        while (!done) {
            int idx = base - lane;
            u64 st = FLAG_PRE;              // idx < 0 acts as prefix 0
            if (idx >= 0) {
                do { st = g_scanstate[idx]; } while ((st >> 62) == 0ULL);
            }
            unsigned pre = __ballot_sync(0xffffffffu, (st >> 62) == 2ULL);
            long long val = (long long)(st & VALMASK);
            long long contrib;
            if (pre) {
                int firstpre = __ffs(pre) - 1;   // nearest prefix (lane 0 = closest block)
                contrib = (lane <= firstpre) ? ((lane < firstpre) ? val : val) : 0;
                if (lane > firstpre) contrib = 0;
                done = true;
            } else {
                contrib = val;
            }
#pragma unroll
            for (int o = 16; o > 0; o >>= 1)
                contrib += __shfl_down_sync(0xffffffffu, contrib, o);
            contrib = __shfl_sync(0xffffffffu, contrib, 0);
            run += contrib;
            base -= 32;
        }
        if (lane == 0) {
            sprefix = (u64)run;
            __threadfence();
            g_scanstate[b] = FLAG_PRE | (u64)(run + (long long)total);
        }
    }
    __syncthreads();
    int P = (int)sprefix;
    if (i < N) {
        g_off[i + 1] = incl + P;
        g_cur[i]     = incl - v + P;
        if (i == 0) g_off[0] = 0;
    }
}

// ---------------------------------------------------------------------------
// kD: place src ids into CSR slots
// ---------------------------------------------------------------------------
__global__ void kD_place(const int* __restrict__ ei, int E)
{
    int e = blockIdx.x * blockDim.x + threadIdx.x;
    if (e >= E) return;
    int s = ei[e];
    int d = ei[E + e];
    int pos = atomicAdd(&g_cur[d], 1);
    g_srcidx[pos] = s;
}

// ---------------------------------------------------------------------------
// kE: gather-aggregate. 16 threads per node; each owns one float4 channel
// group. Coalesced reads of x (L2-resident), no feature atomics.
// ---------------------------------------------------------------------------
__global__ __launch_bounds__(256) void kE_gather(const float* __restrict__ x, int N)
{
    int gidx = blockIdx.x * 256 + threadIdx.x;
    int n  = gidx >> 4;
    int c4 = gidx & 15;
    if (n >= N) return;
    int off = g_off[n], end = g_off[n + 1];

    const float4* x4 = reinterpret_cast<const float4*>(x);
    float4 a0 = make_float4(0.f, 0.f, 0.f, 0.f);
    float4 a1 = a0;

    int k = off;
    for (; k + 1 < end; k += 2) {
        int s0 = g_srcidx[k];
        int s1 = g_srcidx[k + 1];
        float4 v0 = __ldg(x4 + (size_t)s0 * 16 + c4);
        float4 v1 = __ldg(x4 + (size_t)s1 * 16 + c4);
        a0.x += v0.x; a0.y += v0.y; a0.z += v0.z; a0.w += v0.w;
        a1.x += v1.x; a1.y += v1.y; a1.z += v1.z; a1.w += v1.w;
    }
    if (k < end) {
        int s0 = g_srcidx[k];
        float4 v0 = __ldg(x4 + (size_t)s0 * 16 + c4);
        a0.x += v0.x; a0.y += v0.y; a0.z += v0.z; a0.w += v0.w;
    }
    a0.x += a1.x; a0.y += a1.y; a0.z += a1.z; a0.w += a1.w;

    reinterpret_cast<float4*>(g_agg)[(size_t)n * 16 + c4] = a0;
    if (c4 == 0) g_deg[n] = (float)(end - off);
}

// ---------------------------------------------------------------------------
// K2: per-node fused GEMM using packed f32x2 FMA:
//   h = (agg/max(deg,1)) @ Wl^T + bl + x @ Wr^T        -> g_h
//   tact = relu(x @ a1_w^T + a1_b)                      -> g_tact
// ---------------------------------------------------------------------------
__global__ __launch_bounds__(256) void k2_node_gemm(
    const float* __restrict__ x,
    const float* __restrict__ Wl, const float* __restrict__ bl,
    const float* __restrict__ Wr,
    const float* __restrict__ a1w, const float* __restrict__ a1b, int N)
{
    __shared__ __align__(16) float sWl[64][64];  // [k][j] = Wl[j][k]
    __shared__ __align__(16) float sWr[64][64];  // [k][j] = Wr[j][k]
    __shared__ __align__(16) float sA1[64][8];   // [k][r] = a1w[r][k]
    __shared__ __align__(16) float sBl[64];

    for (int i = threadIdx.x; i < 4096; i += 256) {
        int j = i & 63, k = i >> 6;
        sWl[k][j] = Wl[j * 64 + k];
        sWr[k][j] = Wr[j * 64 + k];
    }
    for (int i = threadIdx.x; i < 512; i += 256) {
        int r = i & 7, k = i >> 3;
        sA1[k][r] = a1w[r * 64 + k];
    }
    if (threadIdx.x < 64) sBl[threadIdx.x] = bl[threadIdx.x];
    __syncthreads();

    int n = blockIdx.x * 256 + threadIdx.x;
    if (n >= N) return;

    u64 acc[32];
    {
        const float2* blp = reinterpret_cast<const float2*>(sBl);
#pragma unroll
        for (int j = 0; j < 32; j++) { float2 v = blp[j]; acc[j] = pack2(v.x, v.y); }
    }
    u64 t2[4];
#pragma unroll
    for (int r = 0; r < 4; r++) t2[r] = pack2(__ldg(a1b + 2 * r), __ldg(a1b + 2 * r + 1));

    float inv = 1.0f / fmaxf(g_deg[n], 1.0f);
    const float4* xr = reinterpret_cast<const float4*>(x) + (size_t)n * 16;
    const float4* ar = reinterpret_cast<const float4*>(g_agg) + (size_t)n * 16;

#pragma unroll 1
    for (int k4 = 0; k4 < 16; k4++) {
        float4 xv = __ldg(xr + k4);
        float4 av = ar[k4];
        float ax[4] = { av.x * inv, av.y * inv, av.z * inv, av.w * inv };
        float xx4[4] = { xv.x, xv.y, xv.z, xv.w };
#pragma unroll
        for (int kk = 0; kk < 4; kk++) {
            int k = k4 * 4 + kk;
            u64 aa = pack2(ax[kk], ax[kk]);
            u64 xx = pack2(xx4[kk], xx4[kk]);
            const ulonglong2* wl2 = reinterpret_cast<const ulonglong2*>(&sWl[k][0]);
            const ulonglong2* wr2 = reinterpret_cast<const ulonglong2*>(&sWr[k][0]);
#pragma unroll
            for (int j4 = 0; j4 < 16; j4++) {
                ulonglong2 wlv = wl2[j4];
                ulonglong2 wrv = wr2[j4];
                acc[2 * j4 + 0] = fma2(aa, wlv.x, fma2(xx, wrv.x, acc[2 * j4 + 0]));
                acc[2 * j4 + 1] = fma2(aa, wlv.y, fma2(xx, wrv.y, acc[2 * j4 + 1]));
            }
            const ulonglong2* a12 = reinterpret_cast<const ulonglong2*>(&sA1[k][0]);
            ulonglong2 a1lo = a12[0];
            ulonglong2 a1hi = a12[1];
            t2[0] = fma2(xx, a1lo.x, t2[0]);
            t2[1] = fma2(xx, a1lo.y, t2[1]);
            t2[2] = fma2(xx, a1hi.x, t2[2]);
            t2[3] = fma2(xx, a1hi.y, t2[3]);
        }
    }

    float4* hr = reinterpret_cast<float4*>(g_h) + (size_t)n * 16;
#pragma unroll
    for (int j4 = 0; j4 < 16; j4++) {
        float2 a = unpack2(acc[2 * j4 + 0]);
        float2 b = unpack2(acc[2 * j4 + 1]);
        hr[j4] = make_float4(a.x, a.y, b.x, b.y);
    }

    float2 p0 = unpack2(t2[0]), p1 = unpack2(t2[1]);
    float2 p2 = unpack2(t2[2]), p3 = unpack2(t2[3]);
    float4* tr = reinterpret_cast<float4*>(g_tact) + (size_t)n * 2;
    tr[0] = make_float4(fmaxf(p0.x, 0.f), fmaxf(p0.y, 0.f), fmaxf(p1.x, 0.f), fmaxf(p1.y, 0.f));
    tr[1] = make_float4(fmaxf(p2.x, 0.f), fmaxf(p2.y, 0.f), fmaxf(p3.x, 0.f), fmaxf(p3.y, 0.f));
}

// ---------------------------------------------------------------------------
// k2b: per-graph stats, 8 slices/graph (grid=2048). Partial reduce into
// g_stat via red.add.v4; last-arriving block per graph finalizes mean/rstd.
// ---------------------------------------------------------------------------
__global__ __launch_bounds__(256) void k2b_part(
    const int* __restrict__ batch, const float* __restrict__ gn_alpha, int N)
{
    int g     = blockIdx.x >> 3;
    int c4 = threadIdx.x & 15;
    int r  = threadIdx.x >> 4;
    int slice = blockIdx.x & 7;

    int lo = 0, hi = N;
    while (lo < hi) { int mid = (lo + hi) >> 1; if (batch[mid] < g) lo = mid + 1; else hi = mid; }
    int start = lo;
    lo = start; hi = N;
    while (lo < hi) { int mid = (lo + hi) >> 1; if (batch[mid] < g + 1) lo = mid + 1; else hi = mid; }
    int end = lo;

    const float4* h4 = reinterpret_cast<const float4*>(g_h);
    float4 s0 = make_float4(0.f, 0.f, 0.f, 0.f), q0 = s0;

    for (int i = start + slice * 16 + r; i < end; i += 128) {
        float4 a = h4[(size_t)i * 16 + c4];
        s0.x += a.x; s0.y += a.y; s0.z += a.z; s0.w += a.w;
        q0.x = fmaf(a.x, a.x, q0.x); q0.y = fmaf(a.y, a.y, q0.y);
        q0.z = fmaf(a.z, a.z, q0.z); q0.w = fmaf(a.w, a.w, q0.w);
    }

    __shared__ __align__(16) float4 sS[16][16];
    __shared__ __align__(16) float4 sQ[16][16];
    sS[r][c4] = s0;
    sQ[r][c4] = q0;
    __syncthreads();
    for (int off = 8; off > 0; off >>= 1) {
        if (r < off) {
            float4 a = sS[r][c4], b = sS[r + off][c4];
            sS[r][c4] = make_float4(a.x + b.x, a.y + b.y, a.z + b.z, a.w + b.w);
            float4 c = sQ[r][c4], d = sQ[r + off][c4];
            sQ[r][c4] = make_float4(c.x + d.x, c.y + d.y, c.z + d.z, c.w + d.w);
        }
        __syncthreads();
    }
    if (r == 0) {
        red_add_v4(&g_stat[g * 128 + c4 * 4], sS[0][c4]);
        red_add_v4(&g_stat[g * 128 + 64 + c4 * 4], sQ[0][c4]);
        __threadfence();   // order REDs before the counter increment
    }
    __syncthreads();
    __shared__ int slast;
    if (threadIdx.x == 0) slast = (atomicAdd(&g_k2b_ctr[g], 1) == 7) ? 1 : 0;
    __syncthreads();
    if (slast && threadIdx.x < 64) {
        __threadfence();   // acquire side
        int c = threadIdx.x;
        float cnt = fmaxf((float)(end - start), 1.0f);
        float rinv = 1.0f / cnt;
        float sum = g_stat[g * 128 + c];
        float sq  = g_stat[g * 128 + 64 + c];
        float mu = sum * rinv;
        float al = gn_alpha[c];
        float fac = 2.0f * al - al * al;
        float var = fmaxf(sq * rinv - fac * mu * mu, 0.0f);
        g_mean[g * 64 + c] = mu;
        g_rstd[g * 64 + c] = rsqrtf(var + EPS);
    }
}

// ---------------------------------------------------------------------------
// K3: finalize. thread per (node, 4-channel chunk).
// ---------------------------------------------------------------------------
__device__ __forceinline__ float f4get(const float4& v, int u)
{
    switch (u) { case 0: return v.x; case 1: return v.y; case 2: return v.z; default: return v.w; }
}

__global__ __launch_bounds__(256) void k3_finalize(
    const float* __restrict__ x, const int* __restrict__ batch,
    const float* __restrict__ gnw, const float* __restrict__ gnb,
    const float* __restrict__ gna,
    const float* __restrict__ a2w, const float* __restrict__ a2b,
    float* __restrict__ out, int N)
{
    int i = blockIdx.x * blockDim.x + threadIdx.x;
    if (i >= N * 16) return;
    int n  = i >> 4;
    int c4 = i & 15;
    int g  = batch[n];

    float4 hv = reinterpret_cast<const float4*>(g_h)[(size_t)n * 16 + c4];
    float4 xv = reinterpret_cast<const float4*>(x)[(size_t)n * 16 + c4];
    float4 mu = reinterpret_cast<const float4*>(g_mean)[g * 16 + c4];
    float4 rs = reinterpret_cast<const float4*>(g_rstd)[g * 16 + c4];
    float4 al = __ldg(reinterpret_cast<const float4*>(gna) + c4);
    float4 w4 = __ldg(reinterpret_cast<const float4*>(gnw) + c4);
    float4 b4 = __ldg(reinterpret_cast<const float4*>(gnb) + c4);
    float4 t0 = reinterpret_cast<const float4*>(g_tact)[(size_t)n * 2];
    float4 t1 = reinterpret_cast<const float4*>(g_tact)[(size_t)n * 2 + 1];
    float4 b2 = __ldg(reinterpret_cast<const float4*>(a2b) + c4);

    float res[4];
#pragma unroll
    for (int u = 0; u < 4; u++) {
        int j = c4 * 4 + u;
        float4 wa = __ldg(reinterpret_cast<const float4*>(a2w) + j * 2);
        float4 wb = __ldg(reinterpret_cast<const float4*>(a2w) + j * 2 + 1);
        float z = wa.x * t0.x + wa.y * t0.y + wa.z * t0.z + wa.w * t0.w
                + wb.x * t1.x + wb.y * t1.y + wb.z * t1.z + wb.w * t1.w
                + f4get(b2, u);
        float gate = 1.0f / (1.0f + __expf(-z));
        float y = f4get(w4, u) * (f4get(hv, u) - f4get(mu, u) * f4get(al, u)) * f4get(rs, u)
                + f4get(b4, u);
        res[u] = fmaxf(y + gate * f4get(xv, u), 0.0f);
    }
    reinterpret_cast<float4*>(out)[(size_t)n * 16 + c4] =
        make_float4(res[0], res[1], res[2], res[3]);
}

// ---------------------------------------------------------------------------
// launch (8 kernels)
// ---------------------------------------------------------------------------
extern "C" void kernel_launch(void* const* d_in, const int* in_sizes, int n_in,
                              void* d_out, int out_size)
{
    const float* x     = (const float*)d_in[0];
    const int*   ei    = (const int*)d_in[1];     // int32 (JAX x64 disabled)
    const int*   batch = (const int*)d_in[2];     // int32
    const float* Wl    = (const float*)d_in[3];
    const float* bl    = (const float*)d_in[4];
    const float* Wr    = (const float*)d_in[5];
    const float* gnw   = (const float*)d_in[6];
    const float* gnb   = (const float*)d_in[7];
    const float* gna   = (const float*)d_in[8];
    const float* a1w   = (const float*)d_in[9];
    const float* a1b   = (const float*)d_in[10];
    const float* a2w   = (const float*)d_in[11];
    const float* a2b   = (const float*)d_in[12];
    float*       out   = (float*)d_out;

    int N = in_sizes[0] / CC;          // 100000
    int E = in_sizes[1] / 2;           // 1200000
    int nb = (N + 255) / 256;          // 391 scan blocks

    kA_zero<<<(N + 255) / 256, 256>>>(N);
    kB_hist<<<(E + 255) / 256, 256>>>(ei, E);
    kScan<<<nb, 256>>>(N);
    kD_place<<<(E + 255) / 256, 256>>>(ei, E);
    kE_gather<<<(N * 16 + 255) / 256, 256>>>(x, N);
    k2_node_gemm<<<(N + 255) / 256, 256>>>(x, Wl, bl, Wr, a1w, a1b, N);
    k2b_part<<<GG * 8, 256>>>(batch, gna, N);
    k3_finalize<<<(N * 16 + 255) / 256, 256>>>(x, batch, gnw, gnb, gna, a2w, a2b, out, N);
}

// round 12
// speedup vs baseline: 1.1255x; 1.0001x over previous
#include <cuda_runtime.h>
#include <cuda_bf16.h>
#include <stdint.h>

// Problem constants (fixed by the dataset)
#define NN 100000
#define CC 64
#define EE 1200000
#define GG 256
#define EPS 1e-5f

typedef unsigned long long u64;

#define FLAG_AGG (1ULL << 62)
#define FLAG_PRE (2ULL << 62)
#define VALMASK  ((1ULL << 62) - 1ULL)

// ---------------------------------------------------------------------------
// Scratch (device globals; loader zero-initialized; each call re-zeroes what
// it dirties AFTER last use so the graph stays deterministic).
// ---------------------------------------------------------------------------
__device__ __align__(16) float g_agg[NN * CC];    // neighbor-sum (gather output)
__device__ __align__(16) float g_deg[NN];         // in-degree (float)
__device__ __align__(16) float g_h[NN * CC];      // SAGE output
__device__ __align__(16) float g_tact[NN * 8];    // relu(x @ a1^T + a1_b)
__device__ __align__(16) float g_mean[GG * CC];   // per-graph mean
__device__ __align__(16) float g_rstd[GG * CC];   // per-graph rsqrt(var+eps)
__device__ __align__(16) float g_stat[GG * 128];  // per-graph partial sum[64]|sq[64]

__device__ __align__(16) int g_cnt[NN];           // in-degree counts (zeroed by kD)
__device__ __align__(16) int g_off[NN + 1];       // CSR offsets
__device__ __align__(16) int g_cur[NN];           // placement cursors
__device__ __align__(16) int g_srcidx[EE];        // CSR: src node per slot
__device__ int g_k2b_ctr[GG];                     // last-block counters (zeroed by kE)
__device__ volatile u64 g_scanstate[512];         // lookback state (zeroed by kD)

// ---------------------------------------------------------------------------
// f32x2 packed math (PTX-only path)
// ---------------------------------------------------------------------------
__device__ __forceinline__ u64 pack2(float lo, float hi)
{
    u64 r;
    asm("mov.b64 %0, {%1, %2};" : "=l"(r)
        : "r"(__float_as_uint(lo)), "r"(__float_as_uint(hi)));
    return r;
}
__device__ __forceinline__ u64 fma2(u64 a, u64 b, u64 c)
{
    u64 d;
    asm("fma.rn.f32x2 %0, %1, %2, %3;" : "=l"(d) : "l"(a), "l"(b), "l"(c));
    return d;
}
__device__ __forceinline__ float2 unpack2(u64 v)
{
    float2 r;
    uint32_t lo, hi;
    asm("mov.b64 {%0, %1}, %2;" : "=r"(lo), "=r"(hi) : "l"(v));
    r.x = __uint_as_float(lo);
    r.y = __uint_as_float(hi);
    return r;
}

__device__ __forceinline__ void red_add_v4(float* addr, float4 v)
{
    asm volatile("red.global.add.v4.f32 [%0], {%1, %2, %3, %4};"
                 :: "l"(addr), "f"(v.x), "f"(v.y), "f"(v.z), "f"(v.w)
                 : "memory");
}

// ---------------------------------------------------------------------------
// kB: histogram of in-degree. 4 edges/thread (MLP=4).
// g_cnt was zeroed by previous call's kD (loader-zero on first call).
// ---------------------------------------------------------------------------
__global__ void kB_hist(const int* __restrict__ ei, int E)
{
    int base = (blockIdx.x * blockDim.x + threadIdx.x) * 4;
#pragma unroll
    for (int u = 0; u < 4; u++) {
        int e = base + u;
        if (e < E) atomicAdd(&g_cnt[ei[E + e]], 1);
    }
}

// ---------------------------------------------------------------------------
// kScan: single-pass exclusive scan of g_cnt -> g_off[N+1], g_cur
// (decoupled lookback, warp-parallel 32-wide windows)
// ---------------------------------------------------------------------------
__global__ __launch_bounds__(256) void kScan(int N)
{
    int b = blockIdx.x;
    int i = b * 256 + threadIdx.x;
    int lane = threadIdx.x & 31, w = threadIdx.x >> 5;

    int v = (i < N) ? g_cnt[i] : 0;
    int s = v;
#pragma unroll
    for (int o = 1; o < 32; o <<= 1) {
        int t = __shfl_up_sync(0xffffffffu, s, o);
        if (lane >= o) s += t;
    }
    __shared__ int wsum[8], woff[8], sbtot;
    __shared__ u64 sprefix;
    if (lane == 31) wsum[w] = s;
    __syncthreads();
    if (threadIdx.x == 0) {
        int acc = 0;
#pragma unroll
        for (int k = 0; k < 8; k++) { woff[k] = acc; acc += wsum[k]; }
        sbtot = acc;
        __threadfence();
        g_scanstate[b] = (b == 0 ? FLAG_PRE : FLAG_AGG) | (u64)acc;
        if (b == 0) sprefix = 0ULL;
    }
    __syncthreads();
    int incl = s + woff[w];
    int total = sbtot;

    if (b > 0 && w == 0) {
        long long run = 0;
        int base = b - 1;
        bool done = false;
        while (!done) {
            int idx = base - lane;
            u64 st = FLAG_PRE;
            if (idx >= 0) {
                do { st = g_scanstate[idx]; } while ((st >> 62) == 0ULL);
            }
            unsigned pre = __ballot_sync(0xffffffffu, (st >> 62) == 2ULL);
            long long val = (long long)(st & VALMASK);
            long long contrib;
            if (pre) {
                int firstpre = __ffs(pre) - 1;
                contrib = (lane <= firstpre) ? val : 0;
                done = true;
            } else {
                contrib = val;
            }
#pragma unroll
            for (int o = 16; o > 0; o >>= 1)
                contrib += __shfl_down_sync(0xffffffffu, contrib, o);
            contrib = __shfl_sync(0xffffffffu, contrib, 0);
            run += contrib;
            base -= 32;
        }
        if (lane == 0) {
            sprefix = (u64)run;
            __threadfence();
            g_scanstate[b] = FLAG_PRE | (u64)(run + (long long)total);
        }
    }
    __syncthreads();
    int P = (int)sprefix;
    if (i < N) {
        g_off[i + 1] = incl + P;
        g_cur[i]     = incl - v + P;
        if (i == 0) g_off[0] = 0;
    }
}

// ---------------------------------------------------------------------------
// kD: place src ids into CSR slots. 4 edges/thread (4 independent
// ATOMG->STG chains, MLP=4). Also re-zeroes g_cnt and g_scanstate
// (both fully consumed by kScan, which completed before this launch).
// ---------------------------------------------------------------------------
__global__ void kD_place(const int* __restrict__ ei, int E, int N)
{
    int t = blockIdx.x * blockDim.x + threadIdx.x;
    if (t < N)   g_cnt[t] = 0;
    if (t < 512) g_scanstate[t] = 0ULL;

    int base = t * 4;
#pragma unroll
    for (int u = 0; u < 4; u++) {
        int e = base + u;
        if (e < E) {
            int s = ei[e];
            int d = ei[E + e];
            int pos = atomicAdd(&g_cur[d], 1);
            g_srcidx[pos] = s;
        }
    }
}

// ---------------------------------------------------------------------------
// kE: gather-aggregate. 16 threads per node; each owns one float4 channel
// group. Also zeroes g_stat / g_k2b_ctr for the k2b stage (runs later).
// ---------------------------------------------------------------------------
__global__ __launch_bounds__(256) void kE_gather(const float* __restrict__ x, int N)
{
    int gidx = blockIdx.x * 256 + threadIdx.x;
    if (gidx < GG * 32) reinterpret_cast<float4*>(g_stat)[gidx] = make_float4(0.f, 0.f, 0.f, 0.f);
    if (gidx < GG) g_k2b_ctr[gidx] = 0;

    int n  = gidx >> 4;
    int c4 = gidx & 15;
    if (n >= N) return;
    int off = g_off[n], end = g_off[n + 1];

    const float4* x4 = reinterpret_cast<const float4*>(x);
    float4 a0 = make_float4(0.f, 0.f, 0.f, 0.f);
    float4 a1 = a0;

    int k = off;
    for (; k + 1 < end; k += 2) {
        int s0 = g_srcidx[k];
        int s1 = g_srcidx[k + 1];
        float4 v0 = __ldg(x4 + (size_t)s0 * 16 + c4);
        float4 v1 = __ldg(x4 + (size_t)s1 * 16 + c4);
        a0.x += v0.x; a0.y += v0.y; a0.z += v0.z; a0.w += v0.w;
        a1.x += v1.x; a1.y += v1.y; a1.z += v1.z; a1.w += v1.w;
    }
    if (k < end) {
        int s0 = g_srcidx[k];
        float4 v0 = __ldg(x4 + (size_t)s0 * 16 + c4);
        a0.x += v0.x; a0.y += v0.y; a0.z += v0.z; a0.w += v0.w;
    }
    a0.x += a1.x; a0.y += a1.y; a0.z += a1.z; a0.w += a1.w;

    reinterpret_cast<float4*>(g_agg)[(size_t)n * 16 + c4] = a0;
    if (c4 == 0) g_deg[n] = (float)(end - off);
}

// ---------------------------------------------------------------------------
// K2: per-node fused GEMM using packed f32x2 FMA.
// ---------------------------------------------------------------------------
__global__ __launch_bounds__(256) void k2_node_gemm(
    const float* __restrict__ x,
    const float* __restrict__ Wl, const float* __restrict__ bl,
    const float* __restrict__ Wr,
    const float* __restrict__ a1w, const float* __restrict__ a1b, int N)
{
    __shared__ __align__(16) float sWl[64][64];  // [k][j] = Wl[j][k]
    __shared__ __align__(16) float sWr[64][64];  // [k][j] = Wr[j][k]
    __shared__ __align__(16) float sA1[64][8];   // [k][r] = a1w[r][k]
    __shared__ __align__(16) float sBl[64];

    for (int i = threadIdx.x; i < 4096; i += 256) {
        int j = i & 63, k = i >> 6;
        sWl[k][j] = Wl[j * 64 + k];
        sWr[k][j] = Wr[j * 64 + k];
    }
    for (int i = threadIdx.x; i < 512; i += 256) {
        int r = i & 7, k = i >> 3;
        sA1[k][r] = a1w[r * 64 + k];
    }
    if (threadIdx.x < 64) sBl[threadIdx.x] = bl[threadIdx.x];
    __syncthreads();

    int n = blockIdx.x * 256 + threadIdx.x;
    if (n >= N) return;

    u64 acc[32];
    {
        const float2* blp = reinterpret_cast<const float2*>(sBl);
#pragma unroll
        for (int j = 0; j < 32; j++) { float2 v = blp[j]; acc[j] = pack2(v.x, v.y); }
    }
    u64 t2[4];
#pragma unroll
    for (int r = 0; r < 4; r++) t2[r] = pack2(__ldg(a1b + 2 * r), __ldg(a1b + 2 * r + 1));

    float inv = 1.0f / fmaxf(g_deg[n], 1.0f);
    const float4* xr = reinterpret_cast<const float4*>(x) + (size_t)n * 16;
    const float4* ar = reinterpret_cast<const float4*>(g_agg) + (size_t)n * 16;

#pragma unroll 1
    for (int k4 = 0; k4 < 16; k4++) {
        float4 xv = __ldg(xr + k4);
        float4 av = ar[k4];
        float ax[4] = { av.x * inv, av.y * inv, av.z * inv, av.w * inv };
        float xx4[4] = { xv.x, xv.y, xv.z, xv.w };
#pragma unroll
        for (int kk = 0; kk < 4; kk++) {
            int k = k4 * 4 + kk;
            u64 aa = pack2(ax[kk], ax[kk]);
            u64 xx = pack2(xx4[kk], xx4[kk]);
            const ulonglong2* wl2 = reinterpret_cast<const ulonglong2*>(&sWl[k][0]);
            const ulonglong2* wr2 = reinterpret_cast<const ulonglong2*>(&sWr[k][0]);
#pragma unroll
            for (int j4 = 0; j4 < 16; j4++) {
                ulonglong2 wlv = wl2[j4];
                ulonglong2 wrv = wr2[j4];
                acc[2 * j4 + 0] = fma2(aa, wlv.x, fma2(xx, wrv.x, acc[2 * j4 + 0]));
                acc[2 * j4 + 1] = fma2(aa, wlv.y, fma2(xx, wrv.y, acc[2 * j4 + 1]));
            }
            const ulonglong2* a12 = reinterpret_cast<const ulonglong2*>(&sA1[k][0]);
            ulonglong2 a1lo = a12[0];
            ulonglong2 a1hi = a12[1];
            t2[0] = fma2(xx, a1lo.x, t2[0]);
            t2[1] = fma2(xx, a1lo.y, t2[1]);
            t2[2] = fma2(xx, a1hi.x, t2[2]);
            t2[3] = fma2(xx, a1hi.y, t2[3]);
        }
    }

    float4* hr = reinterpret_cast<float4*>(g_h) + (size_t)n * 16;
#pragma unroll
    for (int j4 = 0; j4 < 16; j4++) {
        float2 a = unpack2(acc[2 * j4 + 0]);
        float2 b = unpack2(acc[2 * j4 + 1]);
        hr[j4] = make_float4(a.x, a.y, b.x, b.y);
    }

    float2 p0 = unpack2(t2[0]), p1 = unpack2(t2[1]);
    float2 p2 = unpack2(t2[2]), p3 = unpack2(t2[3]);
    float4* tr = reinterpret_cast<float4*>(g_tact) + (size_t)n * 2;
    tr[0] = make_float4(fmaxf(p0.x, 0.f), fmaxf(p0.y, 0.f), fmaxf(p1.x, 0.f), fmaxf(p1.y, 0.f));
    tr[1] = make_float4(fmaxf(p2.x, 0.f), fmaxf(p2.y, 0.f), fmaxf(p3.x, 0.f), fmaxf(p3.y, 0.f));
}

// ---------------------------------------------------------------------------
// k2b: per-graph stats, 8 slices/graph (grid=2048). Partial reduce into
// g_stat via red.add.v4; last-arriving block per graph finalizes mean/rstd.
// ---------------------------------------------------------------------------
__global__ __launch_bounds__(256) void k2b_part(
    const int* __restrict__ batch, const float* __restrict__ gn_alpha, int N)
{
    int g     = blockIdx.x >> 3;
    int c4 = threadIdx.x & 15;
    int r  = threadIdx.x >> 4;
    int slice = blockIdx.x & 7;

    int lo = 0, hi = N;
    while (lo < hi) { int mid = (lo + hi) >> 1; if (batch[mid] < g) lo = mid + 1; else hi = mid; }
    int start = lo;
    lo = start; hi = N;
    while (lo < hi) { int mid = (lo + hi) >> 1; if (batch[mid] < g + 1) lo = mid + 1; else hi = mid; }
    int end = lo;

    const float4* h4 = reinterpret_cast<const float4*>(g_h);
    float4 s0 = make_float4(0.f, 0.f, 0.f, 0.f), q0 = s0;

    for (int i = start + slice * 16 + r; i < end; i += 128) {
        float4 a = h4[(size_t)i * 16 + c4];
        s0.x += a.x; s0.y += a.y; s0.z += a.z; s0.w += a.w;
        q0.x = fmaf(a.x, a.x, q0.x); q0.y = fmaf(a.y, a.y, q0.y);
        q0.z = fmaf(a.z, a.z, q0.z); q0.w = fmaf(a.w, a.w, q0.w);
    }

    __shared__ __align__(16) float4 sS[16][16];
    __shared__ __align__(16) float4 sQ[16][16];
    sS[r][c4] = s0;
    sQ[r][c4] = q0;
    __syncthreads();
    for (int off = 8; off > 0; off >>= 1) {
        if (r < off) {
            float4 a = sS[r][c4], b = sS[r + off][c4];
            sS[r][c4] = make_float4(a.x + b.x, a.y + b.y, a.z + b.z, a.w + b.w);
            float4 c = sQ[r][c4], d = sQ[r + off][c4];
            sQ[r][c4] = make_float4(c.x + d.x, c.y + d.y, c.z + d.z, c.w + d.w);
        }
        __syncthreads();
    }
    if (r == 0) {
        red_add_v4(&g_stat[g * 128 + c4 * 4], sS[0][c4]);
        red_add_v4(&g_stat[g * 128 + 64 + c4 * 4], sQ[0][c4]);
        __threadfence();
    }
    __syncthreads();
    __shared__ int slast;
    if (threadIdx.x == 0) slast = (atomicAdd(&g_k2b_ctr[g], 1) == 7) ? 1 : 0;
    __syncthreads();
    if (slast && threadIdx.x < 64) {
        __threadfence();
        int c = threadIdx.x;
        float cnt = fmaxf((float)(end - start), 1.0f);
        float rinv = 1.0f / cnt;
        float sum = g_stat[g * 128 + c];
        float sq  = g_stat[g * 128 + 64 + c];
        float mu = sum * rinv;
        float al = gn_alpha[c];
        float fac = 2.0f * al - al * al;
        float var = fmaxf(sq * rinv - fac * mu * mu, 0.0f);
        g_mean[g * 64 + c] = mu;
        g_rstd[g * 64 + c] = rsqrtf(var + EPS);
    }
}

// ---------------------------------------------------------------------------
// K3: finalize. thread per (node, 4-channel chunk).
// ---------------------------------------------------------------------------
__device__ __forceinline__ float f4get(const float4& v, int u)
{
    switch (u) { case 0: return v.x; case 1: return v.y; case 2: return v.z; default: return v.w; }
}

__global__ __launch_bounds__(256) void k3_finalize(
    const float* __restrict__ x, const int* __restrict__ batch,
    const float* __restrict__ gnw, const float* __restrict__ gnb,
    const float* __restrict__ gna,
    const float* __restrict__ a2w, const float* __restrict__ a2b,
    float* __restrict__ out, int N)
{
    int i = blockIdx.x * blockDim.x + threadIdx.x;
    if (i >= N * 16) return;
    int n  = i >> 4;
    int c4 = i & 15;
    int g  = batch[n];

    float4 hv = reinterpret_cast<const float4*>(g_h)[(size_t)n * 16 + c4];
    float4 xv = reinterpret_cast<const float4*>(x)[(size_t)n * 16 + c4];
    float4 mu = reinterpret_cast<const float4*>(g_mean)[g * 16 + c4];
    float4 rs = reinterpret_cast<const float4*>(g_rstd)[g * 16 + c4];
    float4 al = __ldg(reinterpret_cast<const float4*>(gna) + c4);
    float4 w4 = __ldg(reinterpret_cast<const float4*>(gnw) + c4);
    float4 b4 = __ldg(reinterpret_cast<const float4*>(gnb) + c4);
    float4 t0 = reinterpret_cast<const float4*>(g_tact)[(size_t)n * 2];
    float4 t1 = reinterpret_cast<const float4*>(g_tact)[(size_t)n * 2 + 1];
    float4 b2 = __ldg(reinterpret_cast<const float4*>(a2b) + c4);

    float res[4];
#pragma unroll
    for (int u = 0; u < 4; u++) {
        int j = c4 * 4 + u;
        float4 wa = __ldg(reinterpret_cast<const float4*>(a2w) + j * 2);
        float4 wb = __ldg(reinterpret_cast<const float4*>(a2w) + j * 2 + 1);
        float z = wa.x * t0.x + wa.y * t0.y + wa.z * t0.z + wa.w * t0.w
                + wb.x * t1.x + wb.y * t1.y + wb.z * t1.z + wb.w * t1.w
                + f4get(b2, u);
        float gate = 1.0f / (1.0f + __expf(-z));
        float y = f4get(w4, u) * (f4get(hv, u) - f4get(mu, u) * f4get(al, u)) * f4get(rs, u)
                + f4get(b4, u);
        res[u] = fmaxf(y + gate * f4get(xv, u), 0.0f);
    }
    reinterpret_cast<float4*>(out)[(size_t)n * 16 + c4] =
        make_float4(res[0], res[1], res[2], res[3]);
}

// ---------------------------------------------------------------------------
// launch (7 kernels; 4th = kE_gather, which the profiler captures)
// ---------------------------------------------------------------------------
extern "C" void kernel_launch(void* const* d_in, const int* in_sizes, int n_in,
                              void* d_out, int out_size)
{
    const float* x     = (const float*)d_in[0];
    const int*   ei    = (const int*)d_in[1];     // int32 (JAX x64 disabled)
    const int*   batch = (const int*)d_in[2];     // int32
    const float* Wl    = (const float*)d_in[3];
    const float* bl    = (const float*)d_in[4];
    const float* Wr    = (const float*)d_in[5];
    const float* gnw   = (const float*)d_in[6];
    const float* gnb   = (const float*)d_in[7];
    const float* gna   = (const float*)d_in[8];
    const float* a1w   = (const float*)d_in[9];
    const float* a1b   = (const float*)d_in[10];
    const float* a2w   = (const float*)d_in[11];
    const float* a2b   = (const float*)d_in[12];
    float*       out   = (float*)d_out;

    int N = in_sizes[0] / CC;          // 100000
    int E = in_sizes[1] / 2;           // 1200000
    int nb = (N + 255) / 256;          // 391 scan blocks
    int ne4 = ((E + 3) / 4 + 255) / 256;  // edge kernels, 4 edges/thread

    kB_hist<<<ne4, 256>>>(ei, E);
    kScan<<<nb, 256>>>(N);
    kD_place<<<ne4, 256>>>(ei, E, N);
    kE_gather<<<(N * 16 + 255) / 256, 256>>>(x, N);
    k2_node_gemm<<<nb, 256>>>(x, Wl, bl, Wr, a1w, a1b, N);
    k2b_part<<<GG * 8, 256>>>(batch, gna, N);
    k3_finalize<<<(N * 16 + 255) / 256, 256>>>(x, batch, gnw, gnb, gna, a2w, a2b, out, N);
}

// round 13
// speedup vs baseline: 1.2166x; 1.0809x over previous
#include <cuda_runtime.h>
#include <cuda_bf16.h>
#include <stdint.h>

// Problem constants (fixed by the dataset)
#define NN 100000
#define CC 64
#define EE 1200000
#define GG 256
#define EPS 1e-5f

typedef unsigned long long u64;

#define FLAG_AGG (1ULL << 62)
#define FLAG_PRE (2ULL << 62)
#define VALMASK  ((1ULL << 62) - 1ULL)

// ---------------------------------------------------------------------------
// Scratch (device globals; loader zero-initialized; each call re-zeroes what
// it dirties AFTER last use so the graph stays deterministic).
// ---------------------------------------------------------------------------
__device__ __align__(16) float g_agg[NN * CC];    // neighbor-sum (gather output)
__device__ __align__(16) float g_deg[NN];         // in-degree (float)
__device__ __align__(16) float g_h[NN * CC];      // SAGE output
__device__ __align__(16) float g_mean[GG * CC];   // per-graph mean
__device__ __align__(16) float g_rstd[GG * CC];   // per-graph rsqrt(var+eps)
__device__ __align__(16) float g_stat[GG * 128];  // per-graph partial sum[64]|sq[64]

__device__ __align__(16) int g_cnt[NN];           // in-degree counts (zeroed by kD)
__device__ __align__(16) int g_off[NN + 1];       // CSR offsets
__device__ __align__(16) int g_cur[NN];           // placement cursors
__device__ __align__(16) int g_srcidx[EE];        // CSR: src node per slot
__device__ int g_k2b_ctr[GG];                     // last-block counters (zeroed by kE)
__device__ volatile u64 g_scanstate[512];         // lookback state (zeroed by kD)

__device__ __forceinline__ void red_add_v4(float* addr, float4 v)
{
    asm volatile("red.global.add.v4.f32 [%0], {%1, %2, %3, %4};"
                 :: "l"(addr), "f"(v.x), "f"(v.y), "f"(v.z), "f"(v.w)
                 : "memory");
}

// ---------------------------------------------------------------------------
// kB: histogram of in-degree. 4 edges/thread (MLP=4).
// ---------------------------------------------------------------------------
__global__ void kB_hist(const int* __restrict__ ei, int E)
{
    int base = (blockIdx.x * blockDim.x + threadIdx.x) * 4;
#pragma unroll
    for (int u = 0; u < 4; u++) {
        int e = base + u;
        if (e < E) atomicAdd(&g_cnt[ei[E + e]], 1);
    }
}

// ---------------------------------------------------------------------------
// kScan: single-pass exclusive scan of g_cnt -> g_off[N+1], g_cur
// (decoupled lookback, warp-parallel 32-wide windows)
// ---------------------------------------------------------------------------
__global__ __launch_bounds__(256) void kScan(int N)
{
    int b = blockIdx.x;
    int i = b * 256 + threadIdx.x;
    int lane = threadIdx.x & 31, w = threadIdx.x >> 5;

    int v = (i < N) ? g_cnt[i] : 0;
    int s = v;
#pragma unroll
    for (int o = 1; o < 32; o <<= 1) {
        int t = __shfl_up_sync(0xffffffffu, s, o);
        if (lane >= o) s += t;
    }
    __shared__ int wsum[8], woff[8], sbtot;
    __shared__ u64 sprefix;
    if (lane == 31) wsum[w] = s;
    __syncthreads();
    if (threadIdx.x == 0) {
        int acc = 0;
#pragma unroll
        for (int k = 0; k < 8; k++) { woff[k] = acc; acc += wsum[k]; }
        sbtot = acc;
        __threadfence();
        g_scanstate[b] = (b == 0 ? FLAG_PRE : FLAG_AGG) | (u64)acc;
        if (b == 0) sprefix = 0ULL;
    }
    __syncthreads();
    int incl = s + woff[w];
    int total = sbtot;

    if (b > 0 && w == 0) {
        long long run = 0;
        int base = b - 1;
        bool done = false;
        while (!done) {
            int idx = base - lane;
            u64 st = FLAG_PRE;
            if (idx >= 0) {
                do { st = g_scanstate[idx]; } while ((st >> 62) == 0ULL);
            }
            unsigned pre = __ballot_sync(0xffffffffu, (st >> 62) == 2ULL);
            long long val = (long long)(st & VALMASK);
            long long contrib;
            if (pre) {
                int firstpre = __ffs(pre) - 1;
                contrib = (lane <= firstpre) ? val : 0;
                done = true;
            } else {
                contrib = val;
            }
#pragma unroll
            for (int o = 16; o > 0; o >>= 1)
                contrib += __shfl_down_sync(0xffffffffu, contrib, o);
            contrib = __shfl_sync(0xffffffffu, contrib, 0);
            run += contrib;
            base -= 32;
        }
        if (lane == 0) {
            sprefix = (u64)run;
            __threadfence();
            g_scanstate[b] = FLAG_PRE | (u64)(run + (long long)total);
        }
    }
    __syncthreads();
    int P = (int)sprefix;
    if (i < N) {
        g_off[i + 1] = incl + P;
        g_cur[i]     = incl - v + P;
        if (i == 0) g_off[0] = 0;
    }
}

// ---------------------------------------------------------------------------
// kD: place src ids into CSR slots. 4 edges/thread (MLP=4). Also re-zeroes
// g_cnt and g_scanstate (fully consumed by kScan).
// ---------------------------------------------------------------------------
__global__ void kD_place(const int* __restrict__ ei, int E, int N)
{
    int t = blockIdx.x * blockDim.x + threadIdx.x;
    if (t < N)   g_cnt[t] = 0;
    if (t < 512) g_scanstate[t] = 0ULL;

    int base = t * 4;
#pragma unroll
    for (int u = 0; u < 4; u++) {
        int e = base + u;
        if (e < E) {
            int s = ei[e];
            int d = ei[E + e];
            int pos = atomicAdd(&g_cur[d], 1);
            g_srcidx[pos] = s;
        }
    }
}

// ---------------------------------------------------------------------------
// kE: gather-aggregate. 16 threads per node; each owns one float4 channel
// group. Also zeroes g_stat / g_k2b_ctr for the k2b stage.
// ---------------------------------------------------------------------------
__global__ __launch_bounds__(256) void kE_gather(const float* __restrict__ x, int N)
{
    int gidx = blockIdx.x * 256 + threadIdx.x;
    if (gidx < GG * 32) reinterpret_cast<float4*>(g_stat)[gidx] = make_float4(0.f, 0.f, 0.f, 0.f);
    if (gidx < GG) g_k2b_ctr[gidx] = 0;

    int n  = gidx >> 4;
    int c4 = gidx & 15;
    if (n >= N) return;
    int off = g_off[n], end = g_off[n + 1];

    const float4* x4 = reinterpret_cast<const float4*>(x);
    float4 a0 = make_float4(0.f, 0.f, 0.f, 0.f);
    float4 a1 = a0;

    int k = off;
    for (; k + 1 < end; k += 2) {
        int s0 = g_srcidx[k];
        int s1 = g_srcidx[k + 1];
        float4 v0 = __ldg(x4 + (size_t)s0 * 16 + c4);
        float4 v1 = __ldg(x4 + (size_t)s1 * 16 + c4);
        a0.x += v0.x; a0.y += v0.y; a0.z += v0.z; a0.w += v0.w;
        a1.x += v1.x; a1.y += v1.y; a1.z += v1.z; a1.w += v1.w;
    }
    if (k < end) {
        int s0 = g_srcidx[k];
        float4 v0 = __ldg(x4 + (size_t)s0 * 16 + c4);
        a0.x += v0.x; a0.y += v0.y; a0.z += v0.z; a0.w += v0.w;
    }
    a0.x += a1.x; a0.y += a1.y; a0.z += a1.z; a0.w += a1.w;

    reinterpret_cast<float4*>(g_agg)[(size_t)n * 16 + c4] = a0;
    if (c4 == 0) g_deg[n] = (float)(end - off);
}

// ---------------------------------------------------------------------------
// K2: tiled register-blocked GEMM (fp32):
//   h = [agg/deg | x] (N x 128) @ [Wl ; Wr] (128 x 64)^T-ish + bl
// Block: 128 nodes x 64 outputs, 256 threads; thread = 8 nodes x 4 outputs.
// Smem: sA k-major [128][128] (64KB), sW [128][68] padded (34KB) -> 100,352B.
// ---------------------------------------------------------------------------
#define K2_TILE 128
#define SW_STRIDE 68
#define K2_SMEM_BYTES (128 * 128 * 4 + 128 * SW_STRIDE * 4)

__global__ __launch_bounds__(256) void k2_gemm(
    const float* __restrict__ x,
    const float* __restrict__ Wl, const float* __restrict__ bl,
    const float* __restrict__ Wr, int N)
{
    extern __shared__ float smem[];
    float* sA = smem;                 // [k 0..127][node 0..127]
    float* sW = smem + 128 * 128;     // [k 0..127][j 0..63], row stride 68

    int tid = threadIdx.x;
    int n0 = blockIdx.x * K2_TILE;

    // --- fill weights: sW[k][j] = Wl[j][k]; sW[64+k][j] = Wr[j][k]
    for (int idx = tid; idx < 4096; idx += 256) {
        int j = idx >> 6, k = idx & 63;
        float wl = __ldg(Wl + j * 64 + k);
        float wr = __ldg(Wr + j * 64 + k);
        sW[k * SW_STRIDE + j] = wl;
        sW[(64 + k) * SW_STRIDE + j] = wr;
    }

    // --- fill A-tile (k-major, conflict-free STS: lane -> distinct column)
    {
        int nl = tid & 127, half = tid >> 7;
        int n = n0 + nl; if (n >= N) n = N - 1;
        float inv = 1.0f / fmaxf(g_deg[n], 1.0f);
        const float4* ag4 = reinterpret_cast<const float4*>(g_agg) + (size_t)n * 16;
        const float4* xx4 = reinterpret_cast<const float4*>(x) + (size_t)n * 16;
#pragma unroll
        for (int i = 0; i < 8; i++) {
            int c4 = half * 8 + i;
            float4 a = ag4[c4];
            float4 xv = __ldg(xx4 + c4);
            int kb = c4 * 4;
            sA[(kb + 0) * 128 + nl] = a.x * inv;
            sA[(kb + 1) * 128 + nl] = a.y * inv;
            sA[(kb + 2) * 128 + nl] = a.z * inv;
            sA[(kb + 3) * 128 + nl] = a.w * inv;
            sA[(64 + kb + 0) * 128 + nl] = xv.x;
            sA[(64 + kb + 1) * 128 + nl] = xv.y;
            sA[(64 + kb + 2) * 128 + nl] = xv.z;
            sA[(64 + kb + 3) * 128 + nl] = xv.w;
        }
    }
    __syncthreads();

    int tx = tid & 15;   // output quad: j = tx*4..tx*4+3
    int ty = tid >> 4;   // node group: nl = ty*8..ty*8+7

    float acc[8][4];
    {
        float4 blv = __ldg(reinterpret_cast<const float4*>(bl) + tx);
#pragma unroll
        for (int i = 0; i < 8; i++) {
            acc[i][0] = blv.x; acc[i][1] = blv.y; acc[i][2] = blv.z; acc[i][3] = blv.w;
        }
    }

#pragma unroll 4
    for (int k = 0; k < 128; k++) {
        float4 w  = *reinterpret_cast<const float4*>(&sW[k * SW_STRIDE + tx * 4]);
        float4 a0 = *reinterpret_cast<const float4*>(&sA[k * 128 + ty * 8]);
        float4 a1 = *reinterpret_cast<const float4*>(&sA[k * 128 + ty * 8 + 4]);
        float av[8] = { a0.x, a0.y, a0.z, a0.w, a1.x, a1.y, a1.z, a1.w };
#pragma unroll
        for (int i = 0; i < 8; i++) {
            acc[i][0] = fmaf(av[i], w.x, acc[i][0]);
            acc[i][1] = fmaf(av[i], w.y, acc[i][1]);
            acc[i][2] = fmaf(av[i], w.z, acc[i][2]);
            acc[i][3] = fmaf(av[i], w.w, acc[i][3]);
        }
    }

    float4* h4 = reinterpret_cast<float4*>(g_h);
#pragma unroll
    for (int i = 0; i < 8; i++) {
        int n = n0 + ty * 8 + i;
        if (n < N)
            h4[(size_t)n * 16 + tx] = make_float4(acc[i][0], acc[i][1], acc[i][2], acc[i][3]);
    }
}

// ---------------------------------------------------------------------------
// k2b: per-graph stats, 8 slices/graph (grid=2048). Partial reduce into
// g_stat via red.add.v4; last-arriving block per graph finalizes mean/rstd.
// ---------------------------------------------------------------------------
__global__ __launch_bounds__(256) void k2b_part(
    const int* __restrict__ batch, const float* __restrict__ gn_alpha, int N)
{
    int g     = blockIdx.x >> 3;
    int c4 = threadIdx.x & 15;
    int r  = threadIdx.x >> 4;
    int slice = blockIdx.x & 7;

    int lo = 0, hi = N;
    while (lo < hi) { int mid = (lo + hi) >> 1; if (batch[mid] < g) lo = mid + 1; else hi = mid; }
    int start = lo;
    lo = start; hi = N;
    while (lo < hi) { int mid = (lo + hi) >> 1; if (batch[mid] < g + 1) lo = mid + 1; else hi = mid; }
    int end = lo;

    const float4* h4 = reinterpret_cast<const float4*>(g_h);
    float4 s0 = make_float4(0.f, 0.f, 0.f, 0.f), q0 = s0;

    for (int i = start + slice * 16 + r; i < end; i += 128) {
        float4 a = h4[(size_t)i * 16 + c4];
        s0.x += a.x; s0.y += a.y; s0.z += a.z; s0.w += a.w;
        q0.x = fmaf(a.x, a.x, q0.x); q0.y = fmaf(a.y, a.y, q0.y);
        q0.z = fmaf(a.z, a.z, q0.z); q0.w = fmaf(a.w, a.w, q0.w);
    }

    __shared__ __align__(16) float4 sS[16][16];
    __shared__ __align__(16) float4 sQ[16][16];
    sS[r][c4] = s0;
    sQ[r][c4] = q0;
    __syncthreads();
    for (int off = 8; off > 0; off >>= 1) {
        if (r < off) {
            float4 a = sS[r][c4], b = sS[r + off][c4];
            sS[r][c4] = make_float4(a.x + b.x, a.y + b.y, a.z + b.z, a.w + b.w);
            float4 c = sQ[r][c4], d = sQ[r + off][c4];
            sQ[r][c4] = make_float4(c.x + d.x, c.y + d.y, c.z + d.z, c.w + d.w);
        }
        __syncthreads();
    }
    if (r == 0) {
        red_add_v4(&g_stat[g * 128 + c4 * 4], sS[0][c4]);
        red_add_v4(&g_stat[g * 128 + 64 + c4 * 4], sQ[0][c4]);
        __threadfence();
    }
    __syncthreads();
    __shared__ int slast;
    if (threadIdx.x == 0) slast = (atomicAdd(&g_k2b_ctr[g], 1) == 7) ? 1 : 0;
    __syncthreads();
    if (slast && threadIdx.x < 64) {
        __threadfence();
        int c = threadIdx.x;
        float cnt = fmaxf((float)(end - start), 1.0f);
        float rinv = 1.0f / cnt;
        float sum = g_stat[g * 128 + c];
        float sq  = g_stat[g * 128 + 64 + c];
        float mu = sum * rinv;
        float al = gn_alpha[c];
        float fac = 2.0f * al - al * al;
        float var = fmaxf(sq * rinv - fac * mu * mu, 0.0f);
        g_mean[g * 64 + c] = mu;
        g_rstd[g * 64 + c] = rsqrtf(var + EPS);
    }
}

// ---------------------------------------------------------------------------
// K3: finalize with fused channel attention. thread per (node, 4-ch chunk);
// the 16 lanes of a node cooperatively compute tact via shfl_xor reduction.
// N*16 = 1.6M is a multiple of 256 -> every thread active, shuffles safe.
//   tact = relu(x @ a1^T + a1b);  gate = sigmoid(tact @ a2^T + a2b)
//   out  = relu(w*(h - mean*alpha)*rstd + b + gate*x)
// ---------------------------------------------------------------------------
__device__ __forceinline__ float f4get(const float4& v, int u)
{
    switch (u) { case 0: return v.x; case 1: return v.y; case 2: return v.z; default: return v.w; }
}

__global__ __launch_bounds__(256) void k3_finalize(
    const float* __restrict__ x, const int* __restrict__ batch,
    const float* __restrict__ gnw, const float* __restrict__ gnb,
    const float* __restrict__ gna,
    const float* __restrict__ a1w, const float* __restrict__ a1b,
    const float* __restrict__ a2w, const float* __restrict__ a2b,
    float* __restrict__ out, int N)
{
    int i = blockIdx.x * blockDim.x + threadIdx.x;
    int n  = i >> 4;
    int c4 = i & 15;
    int g  = batch[n];

    float4 xv = reinterpret_cast<const float4*>(x)[(size_t)n * 16 + c4];

    // channel-attention layer 1 partials, reduced across the node's 16 lanes
    float t[8];
#pragma unroll
    for (int r = 0; r < 8; r++) {
        float4 a1v = __ldg(reinterpret_cast<const float4*>(a1w) + r * 16 + c4);
        t[r] = xv.x * a1v.x + xv.y * a1v.y + xv.z * a1v.z + xv.w * a1v.w;
    }
#pragma unroll
    for (int m = 1; m < 16; m <<= 1) {
#pragma unroll
        for (int r = 0; r < 8; r++)
            t[r] += __shfl_xor_sync(0xffffffffu, t[r], m);
    }
#pragma unroll
    for (int r = 0; r < 8; r++) t[r] = fmaxf(t[r] + __ldg(a1b + r), 0.0f);

    float4 hv = reinterpret_cast<const float4*>(g_h)[(size_t)n * 16 + c4];
    float4 mu = reinterpret_cast<const float4*>(g_mean)[g * 16 + c4];
    float4 rs = reinterpret_cast<const float4*>(g_rstd)[g * 16 + c4];
    float4 al = __ldg(reinterpret_cast<const float4*>(gna) + c4);
    float4 w4 = __ldg(reinterpret_cast<const float4*>(gnw) + c4);
    float4 b4 = __ldg(reinterpret_cast<const float4*>(gnb) + c4);
    float4 b2 = __ldg(reinterpret_cast<const float4*>(a2b) + c4);

    float res[4];
#pragma unroll
    for (int u = 0; u < 4; u++) {
        int j = c4 * 4 + u;
        float4 wa = __ldg(reinterpret_cast<const float4*>(a2w) + j * 2);
        float4 wb = __ldg(reinterpret_cast<const float4*>(a2w) + j * 2 + 1);
        float z = wa.x * t[0] + wa.y * t[1] + wa.z * t[2] + wa.w * t[3]
                + wb.x * t[4] + wb.y * t[5] + wb.z * t[6] + wb.w * t[7]
                + f4get(b2, u);
        float gate = 1.0f / (1.0f + __expf(-z));
        float y = f4get(w4, u) * (f4get(hv, u) - f4get(mu, u) * f4get(al, u)) * f4get(rs, u)
                + f4get(b4, u);
        res[u] = fmaxf(y + gate * f4get(xv, u), 0.0f);
    }
    reinterpret_cast<float4*>(out)[(size_t)n * 16 + c4] =
        make_float4(res[0], res[1], res[2], res[3]);
}

// ---------------------------------------------------------------------------
// launch (7 kernels; 4th = kE_gather)
// ---------------------------------------------------------------------------
extern "C" void kernel_launch(void* const* d_in, const int* in_sizes, int n_in,
                              void* d_out, int out_size)
{
    const float* x     = (const float*)d_in[0];
    const int*   ei    = (const int*)d_in[1];     // int32 (JAX x64 disabled)
    const int*   batch = (const int*)d_in[2];     // int32
    const float* Wl    = (const float*)d_in[3];
    const float* bl    = (const float*)d_in[4];
    const float* Wr    = (const float*)d_in[5];
    const float* gnw   = (const float*)d_in[6];
    const float* gnb   = (const float*)d_in[7];
    const float* gna   = (const float*)d_in[8];
    const float* a1w   = (const float*)d_in[9];
    const float* a1b   = (const float*)d_in[10];
    const float* a2w   = (const float*)d_in[11];
    const float* a2b   = (const float*)d_in[12];
    float*       out   = (float*)d_out;

    int N = in_sizes[0] / CC;          // 100000
    int E = in_sizes[1] / 2;           // 1200000
    int nb = (N + 255) / 256;          // 391 scan blocks
    int ne4 = ((E + 3) / 4 + 255) / 256;  // edge kernels, 4 edges/thread

    cudaFuncSetAttribute(k2_gemm, cudaFuncAttributeMaxDynamicSharedMemorySize,
                         K2_SMEM_BYTES);

    kB_hist<<<ne4, 256>>>(ei, E);
    kScan<<<nb, 256>>>(N);
    kD_place<<<ne4, 256>>>(ei, E, N);
    kE_gather<<<(N * 16 + 255) / 256, 256>>>(x, N);
    k2_gemm<<<(N + K2_TILE - 1) / K2_TILE, 256, K2_SMEM_BYTES>>>(x, Wl, bl, Wr, N);
    k2b_part<<<GG * 8, 256>>>(batch, gna, N);
    k3_finalize<<<(N * 16 + 255) / 256, 256>>>(x, batch, gnw, gnb, gna,
                                               a1w, a1b, a2w, a2b, out, N);
}